// round 1
// baseline (speedup 1.0000x reference)
#include <cuda_runtime.h>
#include <cuda_bf16.h>
#include <math.h>

// Problem constants
#define BB 2
#define SS 2048
#define HHDIM 2048
#define NHEADS 16
#define KVHEADS 4
#define HDIM 128
#define MM (BB*SS)              // 4096 rows
#define NQKV 3072               // 2048 q + 512 k + 512 v
#define LORA_SCALE 2.0f
#define ATTN_SCALE 0.08838834764831845f

// Scratch (device globals; allowed by harness rules)
__device__ float g_t[MM*48];
__device__ float g_qkv[(size_t)MM*NQKV];
__device__ float g_q[(size_t)BB*NHEADS*SS*HDIM];
__device__ float g_k[(size_t)BB*KVHEADS*SS*HDIM];
__device__ float g_v[(size_t)BB*KVHEADS*SS*HDIM];
__device__ float g_ctx[(size_t)MM*HHDIM];

// ---------------------------------------------------------------------------
// Kernel 1: t[row, 0..47] = x[row,:] @ [qA | kA | vA]
// grid 4096 blocks x 192 threads
// ---------------------------------------------------------------------------
__global__ __launch_bounds__(192) void lora_t_kernel(
    const float* __restrict__ x,
    const float* __restrict__ qA,
    const float* __restrict__ kA,
    const float* __restrict__ vA)
{
    __shared__ float xs[HHDIM];
    __shared__ float part[48][4];
    int row = blockIdx.x;
    const float* xr = x + (size_t)row * HHDIM;
    for (int i = threadIdx.x; i < HHDIM; i += 192) xs[i] = xr[i];
    __syncthreads();

    int j   = threadIdx.x >> 2;   // 0..47
    int qtr = threadIdx.x & 3;    // 0..3
    const float* Acol;
    int jj;
    if (j < 16)       { Acol = qA; jj = j; }
    else if (j < 32)  { Acol = kA; jj = j - 16; }
    else              { Acol = vA; jj = j - 32; }

    float acc = 0.f;
    int h0 = qtr * 512;
    #pragma unroll 4
    for (int hh = h0; hh < h0 + 512; hh++)
        acc += xs[hh] * Acol[hh * 16 + jj];
    part[j][qtr] = acc;
    __syncthreads();

    if (threadIdx.x < 48) {
        int jo = threadIdx.x;
        g_t[(size_t)row * 48 + jo] = part[jo][0] + part[jo][1] + part[jo][2] + part[jo][3];
    }
}

// ---------------------------------------------------------------------------
// Kernel 2: generic SGEMM  C[M,N] = A[M,K] @ W[N,K]^T   (row-major A, W)
// 128x128x16 tiles, 256 threads, 8x8 per thread.
// Weight pointer selected per N-block: n < n0 -> W0, n < n1 -> W1, else W2.
// mode 0: A = Aext (hidden states), C = g_qkv
// mode 1: A = g_ctx,               C = Cext (d_out)
// ---------------------------------------------------------------------------
#define GBM 128
#define GBN 128
#define GBK 16
__global__ __launch_bounds__(256) void sgemm_kernel(
    const float* __restrict__ Aext,
    const float* __restrict__ W0,
    const float* __restrict__ W1,
    const float* __restrict__ W2,
    int n0, int n1,
    float* Cext, int Ksz, int Nsz, int mode)
{
    __shared__ float As[GBK][GBM];
    __shared__ float Bs[GBK][GBN];

    const float* A = mode ? g_ctx : Aext;
    float*       C = mode ? Cext  : g_qkv;

    int bm = blockIdx.y * GBM;
    int bn = blockIdx.x * GBN;
    int tid = threadIdx.x;

    const float* W; int nbase;
    if (bn < n0)      { W = W0; nbase = 0;  }
    else if (bn < n1) { W = W1; nbase = n0; }
    else              { W = W2; nbase = n1; }

    int tr = tid >> 4;   // 0..15
    int tc = tid & 15;   // 0..15

    float acc[8][8];
    #pragma unroll
    for (int i = 0; i < 8; i++)
        #pragma unroll
        for (int j = 0; j < 8; j++) acc[i][j] = 0.f;

    for (int k0 = 0; k0 < Ksz; k0 += GBK) {
        #pragma unroll
        for (int l = 0; l < 2; l++) {
            int idx  = tid + l * 256;       // float4 index, 0..511
            int row  = idx >> 2;            // 0..127
            int col4 = (idx & 3) * 4;       // 0,4,8,12
            float4 va = *(const float4*)&A[(size_t)(bm + row) * Ksz + k0 + col4];
            As[col4 + 0][row] = va.x; As[col4 + 1][row] = va.y;
            As[col4 + 2][row] = va.z; As[col4 + 3][row] = va.w;
            float4 vb = *(const float4*)&W[(size_t)(bn + row - nbase) * Ksz + k0 + col4];
            Bs[col4 + 0][row] = vb.x; Bs[col4 + 1][row] = vb.y;
            Bs[col4 + 2][row] = vb.z; Bs[col4 + 3][row] = vb.w;
        }
        __syncthreads();

        #pragma unroll
        for (int k = 0; k < GBK; k++) {
            float a[8], b[8];
            *(float4*)&a[0] = *(float4*)&As[k][tr * 8 + 0];
            *(float4*)&a[4] = *(float4*)&As[k][tr * 8 + 4];
            *(float4*)&b[0] = *(float4*)&Bs[k][tc * 8 + 0];
            *(float4*)&b[4] = *(float4*)&Bs[k][tc * 8 + 4];
            #pragma unroll
            for (int i = 0; i < 8; i++)
                #pragma unroll
                for (int j = 0; j < 8; j++)
                    acc[i][j] += a[i] * b[j];
        }
        __syncthreads();
    }

    #pragma unroll
    for (int i = 0; i < 8; i++) {
        float* crow = &C[(size_t)(bm + tr * 8 + i) * Nsz + bn + tc * 8];
        #pragma unroll
        for (int j = 0; j < 8; j += 4) {
            float4 v = make_float4(acc[i][j], acc[i][j+1], acc[i][j+2], acc[i][j+3]);
            *(float4*)&crow[j] = v;
        }
    }
}

// ---------------------------------------------------------------------------
// Kernel 3: bias + LoRA + RoPE + scatter to [B, heads, S, HD].
// q gets ATTN_SCALE folded in. One thread per (row, col) of the 3072-wide qkv;
// q/k threads with d>=64 idle (pair handled by d<64 thread).
// ---------------------------------------------------------------------------
__global__ __launch_bounds__(256) void rope_scatter_kernel(
    const float* __restrict__ cosb,
    const float* __restrict__ sinb,
    const float* __restrict__ q_b,
    const float* __restrict__ k_b,
    const float* __restrict__ v_b,
    const float* __restrict__ q_B,
    const float* __restrict__ k_B,
    const float* __restrict__ v_B)
{
    int idx = blockIdx.x * blockDim.x + threadIdx.x;
    int row = idx / NQKV;
    int c   = idx - row * NQKV;
    if (row >= MM) return;
    int b = row >> 11;        // row / 2048
    int s = row & 2047;
    const float* trow = &g_t[(size_t)row * 48];
    const float* qkvrow = &g_qkv[(size_t)row * NQKV];

    if (c < 2048) {                       // Q
        int h = c >> 7, d = c & 127;
        if (d >= 64) return;
        float v1 = qkvrow[c]      + q_b[c];
        float v2 = qkvrow[c + 64] + q_b[c + 64];
        float a1 = 0.f, a2 = 0.f;
        #pragma unroll
        for (int j = 0; j < 16; j++) {
            float tj = trow[j];
            a1 += tj * q_B[j * 2048 + c];
            a2 += tj * q_B[j * 2048 + c + 64];
        }
        v1 += LORA_SCALE * a1; v2 += LORA_SCALE * a2;
        float cd  = cosb[row * HDIM + d],      sd  = sinb[row * HDIM + d];
        float cd2 = cosb[row * HDIM + d + 64], sd2 = sinb[row * HDIM + d + 64];
        float o1 = v1 * cd  - v2 * sd;
        float o2 = v2 * cd2 + v1 * sd2;
        size_t base = (((size_t)b * NHEADS + h) * SS + s) * HDIM;
        g_q[base + d]      = o1 * ATTN_SCALE;
        g_q[base + d + 64] = o2 * ATTN_SCALE;
    } else if (c < 2560) {                // K
        int cc = c - 2048;
        int h = cc >> 7, d = cc & 127;
        if (d >= 64) return;
        float v1 = qkvrow[c]      + k_b[cc];
        float v2 = qkvrow[c + 64] + k_b[cc + 64];
        float a1 = 0.f, a2 = 0.f;
        #pragma unroll
        for (int j = 0; j < 16; j++) {
            float tj = trow[16 + j];
            a1 += tj * k_B[j * 512 + cc];
            a2 += tj * k_B[j * 512 + cc + 64];
        }
        v1 += LORA_SCALE * a1; v2 += LORA_SCALE * a2;
        float cd  = cosb[row * HDIM + d],      sd  = sinb[row * HDIM + d];
        float cd2 = cosb[row * HDIM + d + 64], sd2 = sinb[row * HDIM + d + 64];
        float o1 = v1 * cd  - v2 * sd;
        float o2 = v2 * cd2 + v1 * sd2;
        size_t base = (((size_t)b * KVHEADS + h) * SS + s) * HDIM;
        g_k[base + d]      = o1;
        g_k[base + d + 64] = o2;
    } else {                              // V (no rope)
        int cc = c - 2560;
        int h = cc >> 7, d = cc & 127;
        float v = qkvrow[c] + v_b[cc];
        float a = 0.f;
        #pragma unroll
        for (int j = 0; j < 16; j++)
            a += trow[32 + j] * v_B[j * 512 + cc];
        v += LORA_SCALE * a;
        g_v[(((size_t)b * KVHEADS + h) * SS + s) * HDIM + d] = v;
    }
}

// ---------------------------------------------------------------------------
// Kernel 4: causal flash attention, fp32.
// grid (S/64, NH, B), 256 threads as 16x16.
// Each thread: 4 score rows x 4 score cols; O accum 4 rows x 8 cols.
// ---------------------------------------------------------------------------
#define FA_QS   (64*128)
#define FA_KS   (64*132)
#define FA_VS   (64*132)
#define FA_PS   (64*68)
#define FA_SMEM_FLOATS (FA_QS + FA_KS + FA_VS + FA_PS)
#define FA_SMEM_BYTES  (FA_SMEM_FLOATS * 4)

__global__ __launch_bounds__(256) void flash_attn_kernel()
{
    extern __shared__ float sm[];
    float* Qs = sm;
    float* Ks = Qs + FA_QS;
    float* Vs = Ks + FA_KS;
    float* Ps = Vs + FA_VS;

    int qb = blockIdx.x;
    int h  = blockIdx.y;
    int b  = blockIdx.z;
    int kvh = h >> 2;                 // n_rep = 4
    int tid = threadIdx.x;
    int tr = tid >> 4;                // 0..15
    int tc = tid & 15;                // 0..15

    const float* Qg = g_q + (((size_t)b * NHEADS + h) * SS + qb * 64) * HDIM;
    const float* Kg = g_k + (((size_t)b * KVHEADS + kvh) * SS) * HDIM;
    const float* Vg = g_v + (((size_t)b * KVHEADS + kvh) * SS) * HDIM;

    // load Q tile (64 x 128)
    #pragma unroll
    for (int l = 0; l < 8; l++) {
        int i4 = tid + l * 256;
        int r  = i4 >> 5;
        int c4 = (i4 & 31) * 4;
        *(float4*)&Qs[r * 128 + c4] = *(const float4*)&Qg[r * 128 + c4];
    }

    float m[4], lsum[4], o[4][8];
    #pragma unroll
    for (int i = 0; i < 4; i++) {
        m[i] = -1e30f; lsum[i] = 0.f;
        #pragma unroll
        for (int j = 0; j < 8; j++) o[i][j] = 0.f;
    }

    for (int kb = 0; kb <= qb; kb++) {
        __syncthreads();   // protects Qs (first iter) and Ks/Vs/Ps reuse
        #pragma unroll
        for (int l = 0; l < 8; l++) {
            int i4 = tid + l * 256;
            int r  = i4 >> 5;
            int c4 = (i4 & 31) * 4;
            *(float4*)&Ks[r * 132 + c4] = *(const float4*)&Kg[(size_t)(kb * 64 + r) * 128 + c4];
            *(float4*)&Vs[r * 132 + c4] = *(const float4*)&Vg[(size_t)(kb * 64 + r) * 128 + c4];
        }
        __syncthreads();

        // S = Q K^T  (4x4 per thread)
        float acc[4][4];
        #pragma unroll
        for (int i = 0; i < 4; i++)
            #pragma unroll
            for (int j = 0; j < 4; j++) acc[i][j] = 0.f;

        for (int k0 = 0; k0 < 128; k0 += 4) {
            float av[4][4], bv[4][4];
            #pragma unroll
            for (int i = 0; i < 4; i++)
                *(float4*)av[i] = *(float4*)&Qs[(tr * 4 + i) * 128 + k0];
            #pragma unroll
            for (int j = 0; j < 4; j++)
                *(float4*)bv[j] = *(float4*)&Ks[(tc * 4 + j) * 132 + k0];
            #pragma unroll
            for (int i = 0; i < 4; i++)
                #pragma unroll
                for (int j = 0; j < 4; j++) {
                    acc[i][j] += av[i][0] * bv[j][0];
                    acc[i][j] += av[i][1] * bv[j][1];
                    acc[i][j] += av[i][2] * bv[j][2];
                    acc[i][j] += av[i][3] * bv[j][3];
                }
        }

        if (kb == qb) {   // causal mask on diagonal tile
            #pragma unroll
            for (int i = 0; i < 4; i++)
                #pragma unroll
                for (int j = 0; j < 4; j++)
                    if (tc * 4 + j > tr * 4 + i) acc[i][j] = -1e30f;
        }

        // online softmax
        #pragma unroll
        for (int i = 0; i < 4; i++) {
            float rm = fmaxf(fmaxf(acc[i][0], acc[i][1]), fmaxf(acc[i][2], acc[i][3]));
            #pragma unroll
            for (int off = 1; off < 16; off <<= 1)
                rm = fmaxf(rm, __shfl_xor_sync(0xffffffffu, rm, off));
            float mn = fmaxf(m[i], rm);
            float corr = __expf(m[i] - mn);
            m[i] = mn;
            float rs = 0.f;
            #pragma unroll
            for (int j = 0; j < 4; j++) {
                float p = __expf(acc[i][j] - mn);
                acc[i][j] = p;
                rs += p;
            }
            #pragma unroll
            for (int off = 1; off < 16; off <<= 1)
                rs += __shfl_xor_sync(0xffffffffu, rs, off);
            lsum[i] = lsum[i] * corr + rs;
            #pragma unroll
            for (int j = 0; j < 8; j++) o[i][j] *= corr;
            #pragma unroll
            for (int j = 0; j < 4; j++)
                Ps[(tr * 4 + i) * 68 + tc * 4 + j] = acc[i][j];
        }
        __syncthreads();

        // O += P V
        #pragma unroll 2
        for (int kk = 0; kk < 64; kk++) {
            float vvals[8];
            *(float4*)&vvals[0] = *(float4*)&Vs[kk * 132 + tc * 8];
            *(float4*)&vvals[4] = *(float4*)&Vs[kk * 132 + tc * 8 + 4];
            float pv[4];
            #pragma unroll
            for (int i = 0; i < 4; i++) pv[i] = Ps[(tr * 4 + i) * 68 + kk];
            #pragma unroll
            for (int i = 0; i < 4; i++)
                #pragma unroll
                for (int j = 0; j < 8; j++)
                    o[i][j] += pv[i] * vvals[j];
        }
    }

    // epilogue: normalize and write ctx[b*S + srow][h*128 + d]
    #pragma unroll
    for (int i = 0; i < 4; i++) {
        float inv = 1.0f / lsum[i];
        int srow = qb * 64 + tr * 4 + i;
        float* dst = g_ctx + ((size_t)b * SS + srow) * HHDIM + h * HDIM + tc * 8;
        float4 v0 = make_float4(o[i][0]*inv, o[i][1]*inv, o[i][2]*inv, o[i][3]*inv);
        float4 v1 = make_float4(o[i][4]*inv, o[i][5]*inv, o[i][6]*inv, o[i][7]*inv);
        *(float4*)&dst[0] = v0;
        *(float4*)&dst[4] = v1;
    }
}

// ---------------------------------------------------------------------------
// Launch
// ---------------------------------------------------------------------------
extern "C" void kernel_launch(void* const* d_in, const int* in_sizes, int n_in,
                              void* d_out, int out_size)
{
    const float* x    = (const float*)d_in[0];
    const float* cosb = (const float*)d_in[1];
    const float* sinb = (const float*)d_in[2];
    // d_in[3] attention_mask: pure causal, reimplemented in-kernel
    const float* q_w  = (const float*)d_in[4];
    const float* k_w  = (const float*)d_in[5];
    const float* v_w  = (const float*)d_in[6];
    const float* q_b  = (const float*)d_in[7];
    const float* k_b  = (const float*)d_in[8];
    const float* v_b  = (const float*)d_in[9];
    const float* q_A  = (const float*)d_in[10];
    const float* q_Bm = (const float*)d_in[11];
    const float* k_A  = (const float*)d_in[12];
    const float* k_Bm = (const float*)d_in[13];
    const float* v_A  = (const float*)d_in[14];
    const float* v_Bm = (const float*)d_in[15];
    const float* o_w  = (const float*)d_in[16];
    float* out = (float*)d_out;

    cudaFuncSetAttribute(flash_attn_kernel,
                         cudaFuncAttributeMaxDynamicSharedMemorySize, FA_SMEM_BYTES);

    // 1. LoRA down-projection t = x @ [qA|kA|vA]
    lora_t_kernel<<<MM, 192>>>(x, q_A, k_A, v_A);

    // 2. Raw QKV GEMM -> g_qkv
    sgemm_kernel<<<dim3(NQKV / GBN, MM / GBM), 256>>>(
        x, q_w, k_w, v_w, 2048, 2560, nullptr, HHDIM, NQKV, 0);

    // 3. bias + LoRA-up + RoPE + scatter
    rope_scatter_kernel<<<(MM * NQKV) / 256, 256>>>(
        cosb, sinb, q_b, k_b, v_b, q_Bm, k_Bm, v_Bm);

    // 4. causal flash attention -> g_ctx
    flash_attn_kernel<<<dim3(SS / 64, NHEADS, BB), 256, FA_SMEM_BYTES>>>();

    // 5. output projection -> d_out
    sgemm_kernel<<<dim3(HHDIM / GBN, MM / GBM), 256>>>(
        nullptr, o_w, o_w, o_w, HHDIM, HHDIM, out, HHDIM, HHDIM, 1);
}

// round 3
// speedup vs baseline: 1.4216x; 1.4216x over previous
#include <cuda_runtime.h>
#include <cuda_bf16.h>
#include <cstdint>
#include <math.h>

// Problem constants
#define BB 2
#define SS 2048
#define HHDIM 2048
#define NHEADS 16
#define KVHEADS 4
#define HDIM 128
#define MM (BB*SS)              // 4096 rows
#define NQKV 3072
#define LORA_SCALE 2.0f
#define ATTN_SCALE 0.08838834764831845f

// ---------------------------------------------------------------------------
// Scratch (device globals)
// ---------------------------------------------------------------------------
__device__ __align__(16) float g_t[MM*48];
__device__ __align__(16) float g_qkv[(size_t)MM*NQKV];
__device__ __align__(16) float g_q[(size_t)BB*NHEADS*SS*HDIM];
__device__ __align__(16) float g_k[(size_t)BB*KVHEADS*SS*HDIM];
__device__ __align__(16) float g_v[(size_t)BB*KVHEADS*SS*HDIM];
__device__ __align__(16) __nv_bfloat16 g_xh[(size_t)MM*HHDIM];
__device__ __align__(16) __nv_bfloat16 g_xl[(size_t)MM*HHDIM];
__device__ __align__(16) __nv_bfloat16 g_wqkv_h[(size_t)NQKV*HHDIM];
__device__ __align__(16) __nv_bfloat16 g_wqkv_l[(size_t)NQKV*HHDIM];
__device__ __align__(16) __nv_bfloat16 g_wo_h[(size_t)HHDIM*HHDIM];
__device__ __align__(16) __nv_bfloat16 g_wo_l[(size_t)HHDIM*HHDIM];
__device__ __align__(16) __nv_bfloat16 g_ctx_h[(size_t)MM*HHDIM];
__device__ __align__(16) __nv_bfloat16 g_ctx_l[(size_t)MM*HHDIM];

// ---------------------------------------------------------------------------
// PTX helpers (baseline-PTX only: ldmatrix / mma.sync / cp.async)
// ---------------------------------------------------------------------------
__device__ __forceinline__ uint32_t smem_to_u32(const void* p) {
    uint32_t a;
    asm("{ .reg .u64 t; cvta.to.shared.u64 t, %1; cvt.u32.u64 %0, t; }"
        : "=r"(a) : "l"(p));
    return a;
}
__device__ __forceinline__ void cp_async16(uint32_t sa, const void* gp) {
    asm volatile("cp.async.cg.shared.global [%0], [%1], 16;"
                 :: "r"(sa), "l"(gp) : "memory");
}
__device__ __forceinline__ void cp_commit() {
    asm volatile("cp.async.commit_group;" ::: "memory");
}
template <int N>
__device__ __forceinline__ void cp_wait() {
    asm volatile("cp.async.wait_group %0;" :: "n"(N) : "memory");
}
__device__ __forceinline__ void ldm_x4(uint32_t& r0, uint32_t& r1,
                                       uint32_t& r2, uint32_t& r3, uint32_t addr) {
    asm volatile("ldmatrix.sync.aligned.m8n8.x4.shared.b16 {%0,%1,%2,%3}, [%4];"
                 : "=r"(r0), "=r"(r1), "=r"(r2), "=r"(r3) : "r"(addr));
}
__device__ __forceinline__ void mma_bf16(float* d, const uint32_t* a,
                                         uint32_t b0, uint32_t b1) {
    asm volatile(
        "mma.sync.aligned.m16n8k16.row.col.f32.bf16.bf16.f32 "
        "{%0,%1,%2,%3}, {%4,%5,%6,%7}, {%8,%9}, {%0,%1,%2,%3};"
        : "+f"(d[0]), "+f"(d[1]), "+f"(d[2]), "+f"(d[3])
        : "r"(a[0]), "r"(a[1]), "r"(a[2]), "r"(a[3]), "r"(b0), "r"(b1));
}

// ---------------------------------------------------------------------------
// Kernel: split fp32 -> bf16 hi + bf16 lo
// ---------------------------------------------------------------------------
__global__ __launch_bounds__(256) void split_kernel(
    const float* __restrict__ src,
    __nv_bfloat16* __restrict__ h,
    __nv_bfloat16* __restrict__ l, int n)
{
    int i = (blockIdx.x * 256 + threadIdx.x) * 4;
    if (i >= n) return;
    float4 v = *(const float4*)(src + i);
    float a[4] = {v.x, v.y, v.z, v.w};
    __nv_bfloat16 hh[4], ll[4];
    #pragma unroll
    for (int j = 0; j < 4; j++) {
        hh[j] = __float2bfloat16_rn(a[j]);
        ll[j] = __float2bfloat16_rn(a[j] - __bfloat162float(hh[j]));
    }
    __nv_bfloat162 p0, p1;
    p0.x = hh[0]; p0.y = hh[1]; p1.x = hh[2]; p1.y = hh[3];
    ((__nv_bfloat162*)(h + i))[0] = p0;
    ((__nv_bfloat162*)(h + i))[1] = p1;
    p0.x = ll[0]; p0.y = ll[1]; p1.x = ll[2]; p1.y = ll[3];
    ((__nv_bfloat162*)(l + i))[0] = p0;
    ((__nv_bfloat162*)(l + i))[1] = p1;
}

// ---------------------------------------------------------------------------
// HMMA GEMM: C[M,N] = A[M,K] @ B[N,K]^T via split-bf16 3-pass.
// 128x128x32 tiles, 8 warps (2x4), cp.async double-buffered smem.
// Smem tile stride = 40 bf16 (80B) -> conflict-free ldmatrix ((5r+c)%8 distinct)
// ---------------------------------------------------------------------------
#define GSTRIDE 40                       // bf16 per smem row
#define GTILE_B (128*GSTRIDE*2)          // 10240 bytes
#define GSTAGE_B (4*GTILE_B)             // 40960 bytes (Ah,Al,Bh,Bl)
#define GEMM_SMEM (2*GSTAGE_B)           // 81920 bytes

__global__ __launch_bounds__(256)
void mma_gemm_kernel(const __nv_bfloat16* __restrict__ Ah,
                     const __nv_bfloat16* __restrict__ Al,
                     const __nv_bfloat16* __restrict__ Bh,
                     const __nv_bfloat16* __restrict__ Bl,
                     float* __restrict__ C, int Ksz, int Nsz)
{
    extern __shared__ char smem[];
    uint32_t sbase = smem_to_u32(smem);
    int tid = threadIdx.x;
    int wid = tid >> 5, lane = tid & 31;
    int bm = blockIdx.y * 128, bn = blockIdx.x * 128;
    int wm = wid >> 2, wn = wid & 3;     // warp 64x32 region

    const __nv_bfloat16* gsrc[4] = {
        Ah + (size_t)bm * Ksz, Al + (size_t)bm * Ksz,
        Bh + (size_t)bn * Ksz, Bl + (size_t)bn * Ksz };

    // per-thread copy coords (2 chunks of 16B per tile)
    int r0c = tid >> 2;                  // row for chunk0 (0..63)
    int c0c = tid & 3;                   // col8 index
    auto issue_stage = [&](int s, int k0) {
        #pragma unroll
        for (int t = 0; t < 4; t++) {
            uint32_t tb = sbase + (uint32_t)s * GSTAGE_B + (uint32_t)t * GTILE_B;
            const __nv_bfloat16* g = gsrc[t] + k0;
            cp_async16(tb + (uint32_t)(r0c * 80 + c0c * 16),
                       g + (size_t)r0c * Ksz + c0c * 8);
            cp_async16(tb + (uint32_t)((r0c + 64) * 80 + c0c * 16),
                       g + (size_t)(r0c + 64) * Ksz + c0c * 8);
        }
        cp_commit();
    };

    float acc[4][4][4];
    #pragma unroll
    for (int i = 0; i < 4; i++)
        #pragma unroll
        for (int j = 0; j < 4; j++)
            #pragma unroll
            for (int r = 0; r < 4; r++) acc[i][j][r] = 0.f;

    int nIter = Ksz / 32;
    issue_stage(0, 0);

    for (int it = 0; it < nIter; it++) {
        int cur = it & 1;
        if (it + 1 < nIter) {
            issue_stage(cur ^ 1, (it + 1) * 32);
            cp_wait<1>();
        } else {
            cp_wait<0>();
        }
        __syncthreads();

        uint32_t ahB = sbase + (uint32_t)cur * GSTAGE_B;
        uint32_t alB = ahB + GTILE_B;
        uint32_t bhB = ahB + 2 * GTILE_B;
        uint32_t blB = ahB + 3 * GTILE_B;

        #pragma unroll
        for (int ks = 0; ks < 2; ks++) {
            int k0 = ks * 16;
            // B fragments: 4 n-tiles (8 regs) for hi and lo
            uint32_t bh[8], bl[8];
            #pragma unroll
            for (int p = 0; p < 2; p++) {
                int brow = wn * 32 + p * 16 + ((lane >> 4) << 3) + (lane & 7);
                int bcol = k0 + ((lane >> 3) & 1) * 8;
                uint32_t off = (uint32_t)(brow * 80 + bcol * 2);
                ldm_x4(bh[p*4+0], bh[p*4+1], bh[p*4+2], bh[p*4+3], bhB + off);
                ldm_x4(bl[p*4+0], bl[p*4+1], bl[p*4+2], bl[p*4+3], blB + off);
            }
            #pragma unroll
            for (int mt = 0; mt < 4; mt++) {
                int arow = wm * 64 + mt * 16 + (lane & 15);
                int acol = k0 + ((lane >> 4) & 1) * 8;
                uint32_t off = (uint32_t)(arow * 80 + acol * 2);
                uint32_t a_h[4], a_l[4];
                ldm_x4(a_h[0], a_h[1], a_h[2], a_h[3], ahB + off);
                ldm_x4(a_l[0], a_l[1], a_l[2], a_l[3], alB + off);
                #pragma unroll
                for (int nt = 0; nt < 4; nt++) {
                    mma_bf16(acc[mt][nt], a_h, bh[nt*2], bh[nt*2+1]);
                    mma_bf16(acc[mt][nt], a_h, bl[nt*2], bl[nt*2+1]);
                    mma_bf16(acc[mt][nt], a_l, bh[nt*2], bh[nt*2+1]);
                }
            }
        }
        __syncthreads();
    }

    // epilogue
    #pragma unroll
    for (int mt = 0; mt < 4; mt++) {
        int r0 = bm + wm * 64 + mt * 16 + (lane >> 2);
        #pragma unroll
        for (int nt = 0; nt < 4; nt++) {
            int c = bn + wn * 32 + nt * 8 + (lane & 3) * 2;
            float2 v0 = make_float2(acc[mt][nt][0], acc[mt][nt][1]);
            float2 v1 = make_float2(acc[mt][nt][2], acc[mt][nt][3]);
            *(float2*)&C[(size_t)r0 * Nsz + c]       = v0;
            *(float2*)&C[(size_t)(r0 + 8) * Nsz + c] = v1;
        }
    }
}

// ---------------------------------------------------------------------------
// Kernel: t[row, 0..47] = x[row,:] @ [qA | kA | vA]
// ---------------------------------------------------------------------------
__global__ __launch_bounds__(192) void lora_t_kernel(
    const float* __restrict__ x,
    const float* __restrict__ qA,
    const float* __restrict__ kA,
    const float* __restrict__ vA)
{
    __shared__ float xs[HHDIM];
    __shared__ float part[48][4];
    int row = blockIdx.x;
    const float* xr = x + (size_t)row * HHDIM;
    for (int i = threadIdx.x; i < HHDIM; i += 192) xs[i] = xr[i];
    __syncthreads();

    int j   = threadIdx.x >> 2;
    int qtr = threadIdx.x & 3;
    const float* Acol; int jj;
    if (j < 16)       { Acol = qA; jj = j; }
    else if (j < 32)  { Acol = kA; jj = j - 16; }
    else              { Acol = vA; jj = j - 32; }

    float acc = 0.f;
    int h0 = qtr * 512;
    #pragma unroll 4
    for (int hh = h0; hh < h0 + 512; hh++)
        acc += xs[hh] * Acol[hh * 16 + jj];
    part[j][qtr] = acc;
    __syncthreads();

    if (threadIdx.x < 48) {
        int jo = threadIdx.x;
        g_t[(size_t)row * 48 + jo] = part[jo][0] + part[jo][1] + part[jo][2] + part[jo][3];
    }
}

// ---------------------------------------------------------------------------
// Kernel: bias + LoRA + RoPE + scatter
// ---------------------------------------------------------------------------
__global__ __launch_bounds__(256) void rope_scatter_kernel(
    const float* __restrict__ cosb,
    const float* __restrict__ sinb,
    const float* __restrict__ q_b,
    const float* __restrict__ k_b,
    const float* __restrict__ v_b,
    const float* __restrict__ q_B,
    const float* __restrict__ k_B,
    const float* __restrict__ v_B)
{
    int idx = blockIdx.x * blockDim.x + threadIdx.x;
    int row = idx / NQKV;
    int c   = idx - row * NQKV;
    if (row >= MM) return;
    int b = row >> 11;
    int s = row & 2047;
    const float* trow = &g_t[(size_t)row * 48];
    const float* qkvrow = &g_qkv[(size_t)row * NQKV];

    if (c < 2048) {                       // Q
        int h = c >> 7, d = c & 127;
        if (d >= 64) return;
        float v1 = qkvrow[c]      + q_b[c];
        float v2 = qkvrow[c + 64] + q_b[c + 64];
        float a1 = 0.f, a2 = 0.f;
        #pragma unroll
        for (int j = 0; j < 16; j++) {
            float tj = trow[j];
            a1 += tj * q_B[j * 2048 + c];
            a2 += tj * q_B[j * 2048 + c + 64];
        }
        v1 += LORA_SCALE * a1; v2 += LORA_SCALE * a2;
        float cd  = cosb[row * HDIM + d],      sd  = sinb[row * HDIM + d];
        float cd2 = cosb[row * HDIM + d + 64], sd2 = sinb[row * HDIM + d + 64];
        float o1 = v1 * cd  - v2 * sd;
        float o2 = v2 * cd2 + v1 * sd2;
        size_t base = (((size_t)b * NHEADS + h) * SS + s) * HDIM;
        g_q[base + d]      = o1 * ATTN_SCALE;
        g_q[base + d + 64] = o2 * ATTN_SCALE;
    } else if (c < 2560) {                // K
        int cc = c - 2048;
        int h = cc >> 7, d = cc & 127;
        if (d >= 64) return;
        float v1 = qkvrow[c]      + k_b[cc];
        float v2 = qkvrow[c + 64] + k_b[cc + 64];
        float a1 = 0.f, a2 = 0.f;
        #pragma unroll
        for (int j = 0; j < 16; j++) {
            float tj = trow[16 + j];
            a1 += tj * k_B[j * 512 + cc];
            a2 += tj * k_B[j * 512 + cc + 64];
        }
        v1 += LORA_SCALE * a1; v2 += LORA_SCALE * a2;
        float cd  = cosb[row * HDIM + d],      sd  = sinb[row * HDIM + d];
        float cd2 = cosb[row * HDIM + d + 64], sd2 = sinb[row * HDIM + d + 64];
        float o1 = v1 * cd  - v2 * sd;
        float o2 = v2 * cd2 + v1 * sd2;
        size_t base = (((size_t)b * KVHEADS + h) * SS + s) * HDIM;
        g_k[base + d]      = o1;
        g_k[base + d + 64] = o2;
    } else {                              // V
        int cc = c - 2560;
        int h = cc >> 7, d = cc & 127;
        float v = qkvrow[c] + v_b[cc];
        float a = 0.f;
        #pragma unroll
        for (int j = 0; j < 16; j++)
            a += trow[32 + j] * v_B[j * 512 + cc];
        v += LORA_SCALE * a;
        g_v[(((size_t)b * KVHEADS + h) * SS + s) * HDIM + d] = v;
    }
}

// ---------------------------------------------------------------------------
// Kernel: causal flash attention fp32; epilogue emits ctx bf16 hi/lo.
// ---------------------------------------------------------------------------
#define FA_QS   (64*128)
#define FA_KS   (64*132)
#define FA_VS   (64*132)
#define FA_PS   (64*68)
#define FA_SMEM_FLOATS (FA_QS + FA_KS + FA_VS + FA_PS)
#define FA_SMEM_BYTES  (FA_SMEM_FLOATS * 4)

__global__ __launch_bounds__(256) void flash_attn_kernel()
{
    extern __shared__ float sm[];
    float* Qs = sm;
    float* Ks = Qs + FA_QS;
    float* Vs = Ks + FA_KS;
    float* Ps = Vs + FA_VS;

    int qb = blockIdx.x;
    int h  = blockIdx.y;
    int b  = blockIdx.z;
    int kvh = h >> 2;
    int tid = threadIdx.x;
    int tr = tid >> 4;
    int tc = tid & 15;

    const float* Qg = g_q + (((size_t)b * NHEADS + h) * SS + qb * 64) * HDIM;
    const float* Kg = g_k + (((size_t)b * KVHEADS + kvh) * SS) * HDIM;
    const float* Vg = g_v + (((size_t)b * KVHEADS + kvh) * SS) * HDIM;

    #pragma unroll
    for (int l = 0; l < 8; l++) {
        int i4 = tid + l * 256;
        int r  = i4 >> 5;
        int c4 = (i4 & 31) * 4;
        *(float4*)&Qs[r * 128 + c4] = *(const float4*)&Qg[r * 128 + c4];
    }

    float m[4], lsum[4], o[4][8];
    #pragma unroll
    for (int i = 0; i < 4; i++) {
        m[i] = -1e30f; lsum[i] = 0.f;
        #pragma unroll
        for (int j = 0; j < 8; j++) o[i][j] = 0.f;
    }

    for (int kb = 0; kb <= qb; kb++) {
        __syncthreads();
        #pragma unroll
        for (int l = 0; l < 8; l++) {
            int i4 = tid + l * 256;
            int r  = i4 >> 5;
            int c4 = (i4 & 31) * 4;
            *(float4*)&Ks[r * 132 + c4] = *(const float4*)&Kg[(size_t)(kb * 64 + r) * 128 + c4];
            *(float4*)&Vs[r * 132 + c4] = *(const float4*)&Vg[(size_t)(kb * 64 + r) * 128 + c4];
        }
        __syncthreads();

        float acc[4][4];
        #pragma unroll
        for (int i = 0; i < 4; i++)
            #pragma unroll
            for (int j = 0; j < 4; j++) acc[i][j] = 0.f;

        for (int k0 = 0; k0 < 128; k0 += 4) {
            float av[4][4], bv[4][4];
            #pragma unroll
            for (int i = 0; i < 4; i++)
                *(float4*)av[i] = *(float4*)&Qs[(tr * 4 + i) * 128 + k0];
            #pragma unroll
            for (int j = 0; j < 4; j++)
                *(float4*)bv[j] = *(float4*)&Ks[(tc * 4 + j) * 132 + k0];
            #pragma unroll
            for (int i = 0; i < 4; i++)
                #pragma unroll
                for (int j = 0; j < 4; j++) {
                    acc[i][j] += av[i][0] * bv[j][0];
                    acc[i][j] += av[i][1] * bv[j][1];
                    acc[i][j] += av[i][2] * bv[j][2];
                    acc[i][j] += av[i][3] * bv[j][3];
                }
        }

        if (kb == qb) {
            #pragma unroll
            for (int i = 0; i < 4; i++)
                #pragma unroll
                for (int j = 0; j < 4; j++)
                    if (tc * 4 + j > tr * 4 + i) acc[i][j] = -1e30f;
        }

        #pragma unroll
        for (int i = 0; i < 4; i++) {
            float rm = fmaxf(fmaxf(acc[i][0], acc[i][1]), fmaxf(acc[i][2], acc[i][3]));
            #pragma unroll
            for (int off = 1; off < 16; off <<= 1)
                rm = fmaxf(rm, __shfl_xor_sync(0xffffffffu, rm, off));
            float mn = fmaxf(m[i], rm);
            float corr = __expf(m[i] - mn);
            m[i] = mn;
            float rs = 0.f;
            #pragma unroll
            for (int j = 0; j < 4; j++) {
                float p = __expf(acc[i][j] - mn);
                acc[i][j] = p;
                rs += p;
            }
            #pragma unroll
            for (int off = 1; off < 16; off <<= 1)
                rs += __shfl_xor_sync(0xffffffffu, rs, off);
            lsum[i] = lsum[i] * corr + rs;
            #pragma unroll
            for (int j = 0; j < 8; j++) o[i][j] *= corr;
            #pragma unroll
            for (int j = 0; j < 4; j++)
                Ps[(tr * 4 + i) * 68 + tc * 4 + j] = acc[i][j];
        }
        __syncthreads();

        #pragma unroll 2
        for (int kk = 0; kk < 64; kk++) {
            float vvals[8];
            *(float4*)&vvals[0] = *(float4*)&Vs[kk * 132 + tc * 8];
            *(float4*)&vvals[4] = *(float4*)&Vs[kk * 132 + tc * 8 + 4];
            float pv[4];
            #pragma unroll
            for (int i = 0; i < 4; i++) pv[i] = Ps[(tr * 4 + i) * 68 + kk];
            #pragma unroll
            for (int i = 0; i < 4; i++)
                #pragma unroll
                for (int j = 0; j < 8; j++)
                    o[i][j] += pv[i] * vvals[j];
        }
    }

    // epilogue: normalize, split to bf16 hi/lo for O-projection GEMM
    #pragma unroll
    for (int i = 0; i < 4; i++) {
        float inv = 1.0f / lsum[i];
        int srow = qb * 64 + tr * 4 + i;
        size_t off = ((size_t)b * SS + srow) * HHDIM + h * HDIM + tc * 8;
        __nv_bfloat16 hh[8], ll[8];
        #pragma unroll
        for (int j = 0; j < 8; j++) {
            float val = o[i][j] * inv;
            hh[j] = __float2bfloat16_rn(val);
            ll[j] = __float2bfloat16_rn(val - __bfloat162float(hh[j]));
        }
        #pragma unroll
        for (int j = 0; j < 8; j += 2) {
            __nv_bfloat162 ph2; ph2.x = hh[j]; ph2.y = hh[j+1];
            *(__nv_bfloat162*)(g_ctx_h + off + j) = ph2;
            __nv_bfloat162 pl2; pl2.x = ll[j]; pl2.y = ll[j+1];
            *(__nv_bfloat162*)(g_ctx_l + off + j) = pl2;
        }
    }
}

// ---------------------------------------------------------------------------
// Launch
// ---------------------------------------------------------------------------
extern "C" void kernel_launch(void* const* d_in, const int* in_sizes, int n_in,
                              void* d_out, int out_size)
{
    const float* x    = (const float*)d_in[0];
    const float* cosb = (const float*)d_in[1];
    const float* sinb = (const float*)d_in[2];
    const float* q_w  = (const float*)d_in[4];
    const float* k_w  = (const float*)d_in[5];
    const float* v_w  = (const float*)d_in[6];
    const float* q_b  = (const float*)d_in[7];
    const float* k_b  = (const float*)d_in[8];
    const float* v_b  = (const float*)d_in[9];
    const float* q_A  = (const float*)d_in[10];
    const float* q_Bm = (const float*)d_in[11];
    const float* k_A  = (const float*)d_in[12];
    const float* k_Bm = (const float*)d_in[13];
    const float* v_A  = (const float*)d_in[14];
    const float* v_Bm = (const float*)d_in[15];
    const float* o_w  = (const float*)d_in[16];
    float* out = (float*)d_out;

    void *p_xh, *p_xl, *p_wqh, *p_wql, *p_woh, *p_wol, *p_qkv, *p_ch, *p_cl;
    cudaGetSymbolAddress(&p_xh,  g_xh);
    cudaGetSymbolAddress(&p_xl,  g_xl);
    cudaGetSymbolAddress(&p_wqh, g_wqkv_h);
    cudaGetSymbolAddress(&p_wql, g_wqkv_l);
    cudaGetSymbolAddress(&p_woh, g_wo_h);
    cudaGetSymbolAddress(&p_wol, g_wo_l);
    cudaGetSymbolAddress(&p_qkv, g_qkv);
    cudaGetSymbolAddress(&p_ch,  g_ctx_h);
    cudaGetSymbolAddress(&p_cl,  g_ctx_l);

    cudaFuncSetAttribute(flash_attn_kernel,
                         cudaFuncAttributeMaxDynamicSharedMemorySize, FA_SMEM_BYTES);
    cudaFuncSetAttribute(mma_gemm_kernel,
                         cudaFuncAttributeMaxDynamicSharedMemorySize, GEMM_SMEM);

    // 0. split fp32 -> bf16 hi/lo
    {
        int n = MM * HHDIM;
        split_kernel<<<n / 1024, 256>>>(x, (__nv_bfloat16*)p_xh, (__nv_bfloat16*)p_xl, n);
        int nq = 2048 * 2048;
        split_kernel<<<nq / 1024, 256>>>(q_w, (__nv_bfloat16*)p_wqh, (__nv_bfloat16*)p_wql, nq);
        int nk = 512 * 2048;
        split_kernel<<<nk / 1024, 256>>>(k_w, (__nv_bfloat16*)p_wqh + (size_t)2048*2048,
                                         (__nv_bfloat16*)p_wql + (size_t)2048*2048, nk);
        split_kernel<<<nk / 1024, 256>>>(v_w, (__nv_bfloat16*)p_wqh + (size_t)2560*2048,
                                         (__nv_bfloat16*)p_wql + (size_t)2560*2048, nk);
        int no = 2048 * 2048;
        split_kernel<<<no / 1024, 256>>>(o_w, (__nv_bfloat16*)p_woh, (__nv_bfloat16*)p_wol, no);
    }

    // 1. LoRA down-projection
    lora_t_kernel<<<MM, 192>>>(x, q_A, k_A, v_A);

    // 2. QKV GEMM (HMMA split-bf16 3-pass) -> g_qkv
    mma_gemm_kernel<<<dim3(NQKV / 128, MM / 128), 256, GEMM_SMEM>>>(
        (const __nv_bfloat16*)p_xh, (const __nv_bfloat16*)p_xl,
        (const __nv_bfloat16*)p_wqh, (const __nv_bfloat16*)p_wql,
        (float*)p_qkv, HHDIM, NQKV);

    // 3. bias + LoRA-up + RoPE + scatter
    rope_scatter_kernel<<<(MM * NQKV) / 256, 256>>>(
        cosb, sinb, q_b, k_b, v_b, q_Bm, k_Bm, v_Bm);

    // 4. causal flash attention -> g_ctx_h/l
    flash_attn_kernel<<<dim3(SS / 64, NHEADS, BB), 256, FA_SMEM_BYTES>>>();

    // 5. output projection (HMMA) -> d_out
    mma_gemm_kernel<<<dim3(HHDIM / 128, MM / 128), 256, GEMM_SMEM>>>(
        (const __nv_bfloat16*)p_ch, (const __nv_bfloat16*)p_cl,
        (const __nv_bfloat16*)p_woh, (const __nv_bfloat16*)p_wol,
        out, HHDIM, HHDIM);
}

// round 4
// speedup vs baseline: 2.7802x; 1.9557x over previous
#include <cuda_runtime.h>
#include <cuda_bf16.h>
#include <cstdint>
#include <math.h>

// Problem constants
#define BB 2
#define SS 2048
#define HHDIM 2048
#define NHEADS 16
#define KVHEADS 4
#define HDIM 128
#define MM (BB*SS)              // 4096 rows
#define NQKV 3072
#define LORA_SCALE 2.0f
#define ATTN_SCALE 0.08838834764831845f

// ---------------------------------------------------------------------------
// Scratch (device globals)
// ---------------------------------------------------------------------------
__device__ __align__(16) float g_t[MM*48];
__device__ __align__(16) float g_qkv[(size_t)MM*NQKV];
__device__ __align__(16) __nv_bfloat16 g_qh[(size_t)BB*NHEADS*SS*HDIM];
__device__ __align__(16) __nv_bfloat16 g_ql[(size_t)BB*NHEADS*SS*HDIM];
__device__ __align__(16) __nv_bfloat16 g_kh[(size_t)BB*KVHEADS*SS*HDIM];
__device__ __align__(16) __nv_bfloat16 g_kl[(size_t)BB*KVHEADS*SS*HDIM];
__device__ __align__(16) __nv_bfloat16 g_vh[(size_t)BB*KVHEADS*SS*HDIM];
__device__ __align__(16) __nv_bfloat16 g_vl[(size_t)BB*KVHEADS*SS*HDIM];
__device__ __align__(16) __nv_bfloat16 g_xh[(size_t)MM*HHDIM];
__device__ __align__(16) __nv_bfloat16 g_xl[(size_t)MM*HHDIM];
__device__ __align__(16) __nv_bfloat16 g_wqkv_h[(size_t)NQKV*HHDIM];
__device__ __align__(16) __nv_bfloat16 g_wqkv_l[(size_t)NQKV*HHDIM];
__device__ __align__(16) __nv_bfloat16 g_wo_h[(size_t)HHDIM*HHDIM];
__device__ __align__(16) __nv_bfloat16 g_wo_l[(size_t)HHDIM*HHDIM];
__device__ __align__(16) __nv_bfloat16 g_ctx_h[(size_t)MM*HHDIM];
__device__ __align__(16) __nv_bfloat16 g_ctx_l[(size_t)MM*HHDIM];

// ---------------------------------------------------------------------------
// PTX helpers (baseline PTX only)
// ---------------------------------------------------------------------------
__device__ __forceinline__ uint32_t smem_to_u32(const void* p) {
    uint32_t a;
    asm("{ .reg .u64 t; cvta.to.shared.u64 t, %1; cvt.u32.u64 %0, t; }"
        : "=r"(a) : "l"(p));
    return a;
}
__device__ __forceinline__ void cp_async16(uint32_t sa, const void* gp) {
    asm volatile("cp.async.cg.shared.global [%0], [%1], 16;"
                 :: "r"(sa), "l"(gp) : "memory");
}
__device__ __forceinline__ void cp_commit() {
    asm volatile("cp.async.commit_group;" ::: "memory");
}
template <int N>
__device__ __forceinline__ void cp_wait() {
    asm volatile("cp.async.wait_group %0;" :: "n"(N) : "memory");
}
__device__ __forceinline__ void ldm_x4(uint32_t* r, uint32_t addr) {
    asm volatile("ldmatrix.sync.aligned.m8n8.x4.shared.b16 {%0,%1,%2,%3}, [%4];"
                 : "=r"(r[0]), "=r"(r[1]), "=r"(r[2]), "=r"(r[3]) : "r"(addr));
}
__device__ __forceinline__ void ldm_x4_t(uint32_t* r, uint32_t addr) {
    asm volatile("ldmatrix.sync.aligned.m8n8.x4.trans.shared.b16 {%0,%1,%2,%3}, [%4];"
                 : "=r"(r[0]), "=r"(r[1]), "=r"(r[2]), "=r"(r[3]) : "r"(addr));
}
__device__ __forceinline__ void mma_bf16(float* d, const uint32_t* a,
                                         uint32_t b0, uint32_t b1) {
    asm volatile(
        "mma.sync.aligned.m16n8k16.row.col.f32.bf16.bf16.f32 "
        "{%0,%1,%2,%3}, {%4,%5,%6,%7}, {%8,%9}, {%0,%1,%2,%3};"
        : "+f"(d[0]), "+f"(d[1]), "+f"(d[2]), "+f"(d[3])
        : "r"(a[0]), "r"(a[1]), "r"(a[2]), "r"(a[3]), "r"(b0), "r"(b1));
}
// split two floats into bf16x2 hi + bf16x2 lo packs (elem0 in low half)
__device__ __forceinline__ void split2(float x, float y, uint32_t& h, uint32_t& l) {
    __nv_bfloat16 hx = __float2bfloat16_rn(x), hy = __float2bfloat16_rn(y);
    h = ((uint32_t)__bfloat16_as_ushort(hy) << 16) | __bfloat16_as_ushort(hx);
    __nv_bfloat16 lx = __float2bfloat16_rn(x - __bfloat162float(hx));
    __nv_bfloat16 ly = __float2bfloat16_rn(y - __bfloat162float(hy));
    l = ((uint32_t)__bfloat16_as_ushort(ly) << 16) | __bfloat16_as_ushort(lx);
}

// ---------------------------------------------------------------------------
// split fp32 -> bf16 hi + lo
// ---------------------------------------------------------------------------
__global__ __launch_bounds__(256) void split_kernel(
    const float* __restrict__ src,
    __nv_bfloat16* __restrict__ h,
    __nv_bfloat16* __restrict__ l, int n)
{
    int i = (blockIdx.x * 256 + threadIdx.x) * 4;
    if (i >= n) return;
    float4 v = *(const float4*)(src + i);
    float a[4] = {v.x, v.y, v.z, v.w};
    uint32_t hp[2], lp[2];
    split2(a[0], a[1], hp[0], lp[0]);
    split2(a[2], a[3], hp[1], lp[1]);
    *(uint2*)(h + i) = make_uint2(hp[0], hp[1]);
    *(uint2*)(l + i) = make_uint2(lp[0], lp[1]);
}

// ---------------------------------------------------------------------------
// HMMA GEMM: C[M,N] = A[M,K] @ B[N,K]^T via split-bf16 3-pass.
// ---------------------------------------------------------------------------
#define GSTRIDE 40
#define GTILE_B (128*GSTRIDE*2)
#define GSTAGE_B (4*GTILE_B)
#define GEMM_SMEM (2*GSTAGE_B)

__global__ __launch_bounds__(256)
void mma_gemm_kernel(const __nv_bfloat16* __restrict__ Ah,
                     const __nv_bfloat16* __restrict__ Al,
                     const __nv_bfloat16* __restrict__ Bh,
                     const __nv_bfloat16* __restrict__ Bl,
                     float* __restrict__ C, int Ksz, int Nsz)
{
    extern __shared__ char smem[];
    uint32_t sbase = smem_to_u32(smem);
    int tid = threadIdx.x;
    int wid = tid >> 5, lane = tid & 31;
    int bm = blockIdx.y * 128, bn = blockIdx.x * 128;
    int wm = wid >> 2, wn = wid & 3;

    const __nv_bfloat16* gsrc[4] = {
        Ah + (size_t)bm * Ksz, Al + (size_t)bm * Ksz,
        Bh + (size_t)bn * Ksz, Bl + (size_t)bn * Ksz };

    int r0c = tid >> 2;
    int c0c = tid & 3;
    auto issue_stage = [&](int s, int k0) {
        #pragma unroll
        for (int t = 0; t < 4; t++) {
            uint32_t tb = sbase + (uint32_t)s * GSTAGE_B + (uint32_t)t * GTILE_B;
            const __nv_bfloat16* g = gsrc[t] + k0;
            cp_async16(tb + (uint32_t)(r0c * 80 + c0c * 16),
                       g + (size_t)r0c * Ksz + c0c * 8);
            cp_async16(tb + (uint32_t)((r0c + 64) * 80 + c0c * 16),
                       g + (size_t)(r0c + 64) * Ksz + c0c * 8);
        }
        cp_commit();
    };

    float acc[4][4][4];
    #pragma unroll
    for (int i = 0; i < 4; i++)
        #pragma unroll
        for (int j = 0; j < 4; j++)
            #pragma unroll
            for (int r = 0; r < 4; r++) acc[i][j][r] = 0.f;

    int nIter = Ksz / 32;
    issue_stage(0, 0);

    for (int it = 0; it < nIter; it++) {
        int cur = it & 1;
        if (it + 1 < nIter) { issue_stage(cur ^ 1, (it + 1) * 32); cp_wait<1>(); }
        else cp_wait<0>();
        __syncthreads();

        uint32_t ahB = sbase + (uint32_t)cur * GSTAGE_B;
        uint32_t alB = ahB + GTILE_B;
        uint32_t bhB = ahB + 2 * GTILE_B;
        uint32_t blB = ahB + 3 * GTILE_B;

        #pragma unroll
        for (int ks = 0; ks < 2; ks++) {
            int k0 = ks * 16;
            uint32_t bh[8], bl[8];
            #pragma unroll
            for (int p = 0; p < 2; p++) {
                int brow = wn * 32 + p * 16 + ((lane >> 4) << 3) + (lane & 7);
                int bcol = k0 + ((lane >> 3) & 1) * 8;
                uint32_t off = (uint32_t)(brow * 80 + bcol * 2);
                ldm_x4(bh + p*4, bhB + off);
                ldm_x4(bl + p*4, blB + off);
            }
            #pragma unroll
            for (int mt = 0; mt < 4; mt++) {
                int arow = wm * 64 + mt * 16 + (lane & 15);
                int acol = k0 + ((lane >> 4) & 1) * 8;
                uint32_t off = (uint32_t)(arow * 80 + acol * 2);
                uint32_t a_h[4], a_l[4];
                ldm_x4(a_h, ahB + off);
                ldm_x4(a_l, alB + off);
                #pragma unroll
                for (int nt = 0; nt < 4; nt++) {
                    mma_bf16(acc[mt][nt], a_h, bh[nt*2], bh[nt*2+1]);
                    mma_bf16(acc[mt][nt], a_h, bl[nt*2], bl[nt*2+1]);
                    mma_bf16(acc[mt][nt], a_l, bh[nt*2], bh[nt*2+1]);
                }
            }
        }
        __syncthreads();
    }

    #pragma unroll
    for (int mt = 0; mt < 4; mt++) {
        int r0 = bm + wm * 64 + mt * 16 + (lane >> 2);
        #pragma unroll
        for (int nt = 0; nt < 4; nt++) {
            int c = bn + wn * 32 + nt * 8 + (lane & 3) * 2;
            *(float2*)&C[(size_t)r0 * Nsz + c]       = make_float2(acc[mt][nt][0], acc[mt][nt][1]);
            *(float2*)&C[(size_t)(r0 + 8) * Nsz + c] = make_float2(acc[mt][nt][2], acc[mt][nt][3]);
        }
    }
}

// ---------------------------------------------------------------------------
// t[row, 0..47] = x[row,:] @ [qA | kA | vA]
// ---------------------------------------------------------------------------
__global__ __launch_bounds__(192) void lora_t_kernel(
    const float* __restrict__ x,
    const float* __restrict__ qA,
    const float* __restrict__ kA,
    const float* __restrict__ vA)
{
    __shared__ float xs[HHDIM];
    __shared__ float part[48][4];
    int row = blockIdx.x;
    const float* xr = x + (size_t)row * HHDIM;
    for (int i = threadIdx.x; i < HHDIM; i += 192) xs[i] = xr[i];
    __syncthreads();

    int j   = threadIdx.x >> 2;
    int qtr = threadIdx.x & 3;
    const float* Acol; int jj;
    if (j < 16)       { Acol = qA; jj = j; }
    else if (j < 32)  { Acol = kA; jj = j - 16; }
    else              { Acol = vA; jj = j - 32; }

    float acc = 0.f;
    int h0 = qtr * 512;
    #pragma unroll 4
    for (int hh = h0; hh < h0 + 512; hh++)
        acc += xs[hh] * Acol[hh * 16 + jj];
    part[j][qtr] = acc;
    __syncthreads();

    if (threadIdx.x < 48) {
        int jo = threadIdx.x;
        g_t[(size_t)row * 48 + jo] = part[jo][0] + part[jo][1] + part[jo][2] + part[jo][3];
    }
}

// ---------------------------------------------------------------------------
// bias + LoRA + RoPE + scatter -> bf16 hi/lo q/k/v
// ---------------------------------------------------------------------------
__global__ __launch_bounds__(256) void rope_scatter_kernel(
    const float* __restrict__ cosb,
    const float* __restrict__ sinb,
    const float* __restrict__ q_b,
    const float* __restrict__ k_b,
    const float* __restrict__ v_b,
    const float* __restrict__ q_B,
    const float* __restrict__ k_B,
    const float* __restrict__ v_B)
{
    int idx = blockIdx.x * blockDim.x + threadIdx.x;
    int row = idx / NQKV;
    int c   = idx - row * NQKV;
    if (row >= MM) return;
    int b = row >> 11;
    int s = row & 2047;
    const float* trow = &g_t[(size_t)row * 48];
    const float* qkvrow = &g_qkv[(size_t)row * NQKV];

    if (c < 2048) {                       // Q
        int h = c >> 7, d = c & 127;
        if (d >= 64) return;
        float v1 = qkvrow[c]      + q_b[c];
        float v2 = qkvrow[c + 64] + q_b[c + 64];
        float a1 = 0.f, a2 = 0.f;
        #pragma unroll
        for (int j = 0; j < 16; j++) {
            float tj = trow[j];
            a1 += tj * q_B[j * 2048 + c];
            a2 += tj * q_B[j * 2048 + c + 64];
        }
        v1 += LORA_SCALE * a1; v2 += LORA_SCALE * a2;
        float cd  = cosb[row * HDIM + d],      sd  = sinb[row * HDIM + d];
        float cd2 = cosb[row * HDIM + d + 64], sd2 = sinb[row * HDIM + d + 64];
        float o1 = (v1 * cd  - v2 * sd)  * ATTN_SCALE;
        float o2 = (v2 * cd2 + v1 * sd2) * ATTN_SCALE;
        size_t base = (((size_t)b * NHEADS + h) * SS + s) * HDIM;
        __nv_bfloat16 h1 = __float2bfloat16_rn(o1);
        __nv_bfloat16 h2 = __float2bfloat16_rn(o2);
        g_qh[base + d]      = h1;
        g_qh[base + d + 64] = h2;
        g_ql[base + d]      = __float2bfloat16_rn(o1 - __bfloat162float(h1));
        g_ql[base + d + 64] = __float2bfloat16_rn(o2 - __bfloat162float(h2));
    } else if (c < 2560) {                // K
        int cc = c - 2048;
        int h = cc >> 7, d = cc & 127;
        if (d >= 64) return;
        float v1 = qkvrow[c]      + k_b[cc];
        float v2 = qkvrow[c + 64] + k_b[cc + 64];
        float a1 = 0.f, a2 = 0.f;
        #pragma unroll
        for (int j = 0; j < 16; j++) {
            float tj = trow[16 + j];
            a1 += tj * k_B[j * 512 + cc];
            a2 += tj * k_B[j * 512 + cc + 64];
        }
        v1 += LORA_SCALE * a1; v2 += LORA_SCALE * a2;
        float cd  = cosb[row * HDIM + d],      sd  = sinb[row * HDIM + d];
        float cd2 = cosb[row * HDIM + d + 64], sd2 = sinb[row * HDIM + d + 64];
        float o1 = v1 * cd  - v2 * sd;
        float o2 = v2 * cd2 + v1 * sd2;
        size_t base = (((size_t)b * KVHEADS + h) * SS + s) * HDIM;
        __nv_bfloat16 h1 = __float2bfloat16_rn(o1);
        __nv_bfloat16 h2 = __float2bfloat16_rn(o2);
        g_kh[base + d]      = h1;
        g_kh[base + d + 64] = h2;
        g_kl[base + d]      = __float2bfloat16_rn(o1 - __bfloat162float(h1));
        g_kl[base + d + 64] = __float2bfloat16_rn(o2 - __bfloat162float(h2));
    } else {                              // V
        int cc = c - 2560;
        int h = cc >> 7, d = cc & 127;
        float v = qkvrow[c] + v_b[cc];
        float a = 0.f;
        #pragma unroll
        for (int j = 0; j < 16; j++)
            a += trow[32 + j] * v_B[j * 512 + cc];
        v += LORA_SCALE * a;
        size_t base = (((size_t)b * KVHEADS + h) * SS + s) * HDIM;
        __nv_bfloat16 hv = __float2bfloat16_rn(v);
        g_vh[base + d] = hv;
        g_vl[base + d] = __float2bfloat16_rn(v - __bfloat162float(hv));
    }
}

// ---------------------------------------------------------------------------
// HMMA causal flash attention. 128 q-rows/CTA, 8 warps x 16 rows, 64-key iters.
// Smem: Q hi/lo (stride 136 bf16) + double-buffered K/V hi/lo stages.
// ---------------------------------------------------------------------------
#define FSTR 272                  // bytes per smem row (136 bf16)
#define FQ_OFF 0
#define FQ_SZ  (128*FSTR)         // 34816 per split
#define FST_OFF (2*FQ_SZ)         // 69632
#define FT_SZ  (64*FSTR)          // 17408 per tile
#define FST_SZ (4*FT_SZ)          // 69632 per stage
#define FA_SMEM (FST_OFF + 2*FST_SZ)   // 208896

__global__ __launch_bounds__(256) void flash_hmma_kernel()
{
    extern __shared__ char smem[];
    uint32_t sb = smem_to_u32(smem);
    int qb = blockIdx.x, h = blockIdx.y, b = blockIdx.z;
    int kvh = h >> 2;
    int tid = threadIdx.x, wid = tid >> 5, lane = tid & 31;

    const __nv_bfloat16* Qh = g_qh + (((size_t)b * NHEADS + h) * SS + qb * 128) * HDIM;
    const __nv_bfloat16* Ql = g_ql + (((size_t)b * NHEADS + h) * SS + qb * 128) * HDIM;
    const __nv_bfloat16* kvsrc[4] = {
        g_kh + ((size_t)b * KVHEADS + kvh) * SS * HDIM,
        g_kl + ((size_t)b * KVHEADS + kvh) * SS * HDIM,
        g_vh + ((size_t)b * KVHEADS + kvh) * SS * HDIM,
        g_vl + ((size_t)b * KVHEADS + kvh) * SS * HDIM };

    // Q: 2 arrays x 128 rows x 16 chunks = 4096
    #pragma unroll
    for (int t = 0; t < 16; t++) {
        int idx = t * 256 + tid;
        int arr = idx >> 11;
        int row = (idx >> 4) & 127;
        int ch  = idx & 15;
        const __nv_bfloat16* src = arr ? Ql : Qh;
        cp_async16(sb + (uint32_t)(arr * FQ_SZ + row * FSTR + ch * 16),
                   src + (size_t)row * 128 + ch * 8);
    }
    auto load_stage = [&](int s, int kv) {
        uint32_t base = sb + FST_OFF + (uint32_t)s * FST_SZ;
        #pragma unroll
        for (int t = 0; t < 16; t++) {
            int idx = t * 256 + tid;
            int arr = idx >> 10;          // 1024 chunks per array
            int row = (idx >> 4) & 63;
            int ch  = idx & 15;
            cp_async16(base + (uint32_t)(arr * FT_SZ + row * FSTR + ch * 16),
                       kvsrc[arr] + (size_t)(kv * 64 + row) * 128 + ch * 8);
        }
        cp_commit();
    };
    load_stage(0, 0);    // group 0 = Q + stage0

    float m[2] = {-1e30f, -1e30f}, lsum[2] = {0.f, 0.f};
    float oacc[16][4];
    #pragma unroll
    for (int g = 0; g < 16; g++)
        #pragma unroll
        for (int r = 0; r < 4; r++) oacc[g][r] = 0.f;

    int wrow0 = wid * 16;
    int rin = lane >> 2;             // 0..7
    int cpair = (lane & 3) * 2;
    int nkv = 2 * qb + 2;

    for (int kv = 0; kv < nkv; kv++) {
        int cur = kv & 1;
        if (kv + 1 < nkv) { load_stage(cur ^ 1, kv + 1); cp_wait<1>(); }
        else cp_wait<0>();
        __syncthreads();

        uint32_t stage = sb + FST_OFF + (uint32_t)cur * FST_SZ;
        uint32_t khB = stage, klB = stage + FT_SZ;
        uint32_t vhB = stage + 2 * FT_SZ, vlB = stage + 3 * FT_SZ;

        // ---- scores S = Q K^T (3-pass split) ----
        float sacc[8][4];
        #pragma unroll
        for (int nt = 0; nt < 8; nt++)
            #pragma unroll
            for (int r = 0; r < 4; r++) sacc[nt][r] = 0.f;

        #pragma unroll
        for (int ks = 0; ks < 8; ks++) {
            int k0 = ks * 16;
            uint32_t qoff = (uint32_t)((wrow0 + (lane & 15)) * FSTR
                                       + (k0 + ((lane >> 4) & 1) * 8) * 2);
            uint32_t qh4[4], ql4[4];
            ldm_x4(qh4, sb + FQ_OFF + qoff);
            ldm_x4(ql4, sb + FQ_SZ + qoff);
            #pragma unroll
            for (int p = 0; p < 4; p++) {
                uint32_t koff = (uint32_t)((p * 16 + ((lane >> 4) << 3) + (lane & 7)) * FSTR
                                           + (k0 + ((lane >> 3) & 1) * 8) * 2);
                uint32_t kh4[4], kl4[4];
                ldm_x4(kh4, khB + koff);
                ldm_x4(kl4, klB + koff);
                mma_bf16(sacc[2*p],   qh4, kh4[0], kh4[1]);
                mma_bf16(sacc[2*p],   qh4, kl4[0], kl4[1]);
                mma_bf16(sacc[2*p],   ql4, kh4[0], kh4[1]);
                mma_bf16(sacc[2*p+1], qh4, kh4[2], kh4[3]);
                mma_bf16(sacc[2*p+1], qh4, kl4[2], kl4[3]);
                mma_bf16(sacc[2*p+1], ql4, kh4[2], kh4[3]);
            }
        }

        // ---- causal mask (last two kv tiles only) ----
        if (kv >= 2 * qb) {
            int row1 = qb * 128 + wrow0 + rin;
            #pragma unroll
            for (int nt = 0; nt < 8; nt++)
                #pragma unroll
                for (int r = 0; r < 4; r++) {
                    int key = kv * 64 + nt * 8 + cpair + (r & 1);
                    int row = (r < 2) ? row1 : row1 + 8;
                    if (key > row) sacc[nt][r] = -1e30f;
                }
        }

        // ---- online softmax ----
        #pragma unroll
        for (int rh = 0; rh < 2; rh++) {
            float rmax = -1e30f;
            #pragma unroll
            for (int nt = 0; nt < 8; nt++)
                rmax = fmaxf(rmax, fmaxf(sacc[nt][rh*2], sacc[nt][rh*2+1]));
            rmax = fmaxf(rmax, __shfl_xor_sync(0xffffffffu, rmax, 1));
            rmax = fmaxf(rmax, __shfl_xor_sync(0xffffffffu, rmax, 2));
            float mn = fmaxf(m[rh], rmax);
            float corr = __expf(m[rh] - mn);
            m[rh] = mn;
            float rs = 0.f;
            #pragma unroll
            for (int nt = 0; nt < 8; nt++) {
                float p0 = __expf(sacc[nt][rh*2]   - mn);
                float p1 = __expf(sacc[nt][rh*2+1] - mn);
                sacc[nt][rh*2] = p0; sacc[nt][rh*2+1] = p1;
                rs += p0 + p1;
            }
            rs += __shfl_xor_sync(0xffffffffu, rs, 1);
            rs += __shfl_xor_sync(0xffffffffu, rs, 2);
            lsum[rh] = lsum[rh] * corr + rs;
            #pragma unroll
            for (int g = 0; g < 16; g++) {
                oacc[g][rh*2]   *= corr;
                oacc[g][rh*2+1] *= corr;
            }
        }

        // ---- pack P into A-frags (hi/lo) ----
        uint32_t pfh[4][4], pfl[4][4];
        #pragma unroll
        for (int j = 0; j < 4; j++) {
            split2(sacc[2*j][0],   sacc[2*j][1],   pfh[j][0], pfl[j][0]);
            split2(sacc[2*j][2],   sacc[2*j][3],   pfh[j][1], pfl[j][1]);
            split2(sacc[2*j+1][0], sacc[2*j+1][1], pfh[j][2], pfl[j][2]);
            split2(sacc[2*j+1][2], sacc[2*j+1][3], pfh[j][3], pfl[j][3]);
        }

        // ---- O += P V (3-pass split), V via ldmatrix.trans ----
        #pragma unroll
        for (int j = 0; j < 4; j++) {
            int k0 = j * 16;
            #pragma unroll
            for (int g = 0; g < 8; g++) {
                uint32_t voff = (uint32_t)((k0 + ((lane >> 3) & 1) * 8 + (lane & 7)) * FSTR
                                           + (g * 16 + ((lane >> 4) & 1) * 8) * 2);
                uint32_t vh4[4], vl4[4];
                ldm_x4_t(vh4, vhB + voff);
                ldm_x4_t(vl4, vlB + voff);
                mma_bf16(oacc[2*g],   pfh[j], vh4[0], vh4[1]);
                mma_bf16(oacc[2*g],   pfh[j], vl4[0], vl4[1]);
                mma_bf16(oacc[2*g],   pfl[j], vh4[0], vh4[1]);
                mma_bf16(oacc[2*g+1], pfh[j], vh4[2], vh4[3]);
                mma_bf16(oacc[2*g+1], pfh[j], vl4[2], vl4[3]);
                mma_bf16(oacc[2*g+1], pfl[j], vh4[2], vh4[3]);
            }
        }
        __syncthreads();
    }

    // ---- epilogue: normalize, split into ctx hi/lo ----
    float inv0 = 1.f / lsum[0], inv1 = 1.f / lsum[1];
    int row1 = qb * 128 + wrow0 + rin;
    #pragma unroll
    for (int g = 0; g < 16; g++) {
        uint32_t h2, l2;
        size_t off0 = ((size_t)b * SS + row1) * HHDIM + h * 128 + g * 8 + cpair;
        split2(oacc[g][0] * inv0, oacc[g][1] * inv0, h2, l2);
        *(uint32_t*)(g_ctx_h + off0) = h2;
        *(uint32_t*)(g_ctx_l + off0) = l2;
        size_t off1 = off0 + (size_t)8 * HHDIM;
        split2(oacc[g][2] * inv1, oacc[g][3] * inv1, h2, l2);
        *(uint32_t*)(g_ctx_h + off1) = h2;
        *(uint32_t*)(g_ctx_l + off1) = l2;
    }
}

// ---------------------------------------------------------------------------
// Launch
// ---------------------------------------------------------------------------
extern "C" void kernel_launch(void* const* d_in, const int* in_sizes, int n_in,
                              void* d_out, int out_size)
{
    const float* x    = (const float*)d_in[0];
    const float* cosb = (const float*)d_in[1];
    const float* sinb = (const float*)d_in[2];
    const float* q_w  = (const float*)d_in[4];
    const float* k_w  = (const float*)d_in[5];
    const float* v_w  = (const float*)d_in[6];
    const float* q_b  = (const float*)d_in[7];
    const float* k_b  = (const float*)d_in[8];
    const float* v_b  = (const float*)d_in[9];
    const float* q_A  = (const float*)d_in[10];
    const float* q_Bm = (const float*)d_in[11];
    const float* k_A  = (const float*)d_in[12];
    const float* k_Bm = (const float*)d_in[13];
    const float* v_A  = (const float*)d_in[14];
    const float* v_Bm = (const float*)d_in[15];
    const float* o_w  = (const float*)d_in[16];
    float* out = (float*)d_out;

    void *p_xh, *p_xl, *p_wqh, *p_wql, *p_woh, *p_wol, *p_qkv, *p_ch, *p_cl;
    cudaGetSymbolAddress(&p_xh,  g_xh);
    cudaGetSymbolAddress(&p_xl,  g_xl);
    cudaGetSymbolAddress(&p_wqh, g_wqkv_h);
    cudaGetSymbolAddress(&p_wql, g_wqkv_l);
    cudaGetSymbolAddress(&p_woh, g_wo_h);
    cudaGetSymbolAddress(&p_wol, g_wo_l);
    cudaGetSymbolAddress(&p_qkv, g_qkv);
    cudaGetSymbolAddress(&p_ch,  g_ctx_h);
    cudaGetSymbolAddress(&p_cl,  g_ctx_l);

    cudaFuncSetAttribute(mma_gemm_kernel,
                         cudaFuncAttributeMaxDynamicSharedMemorySize, GEMM_SMEM);
    cudaFuncSetAttribute(flash_hmma_kernel,
                         cudaFuncAttributeMaxDynamicSharedMemorySize, FA_SMEM);

    // 0. split fp32 -> bf16 hi/lo
    {
        int n = MM * HHDIM;
        split_kernel<<<n / 1024, 256>>>(x, (__nv_bfloat16*)p_xh, (__nv_bfloat16*)p_xl, n);
        int nq = 2048 * 2048;
        split_kernel<<<nq / 1024, 256>>>(q_w, (__nv_bfloat16*)p_wqh, (__nv_bfloat16*)p_wql, nq);
        int nk = 512 * 2048;
        split_kernel<<<nk / 1024, 256>>>(k_w, (__nv_bfloat16*)p_wqh + (size_t)2048*2048,
                                         (__nv_bfloat16*)p_wql + (size_t)2048*2048, nk);
        split_kernel<<<nk / 1024, 256>>>(v_w, (__nv_bfloat16*)p_wqh + (size_t)2560*2048,
                                         (__nv_bfloat16*)p_wql + (size_t)2560*2048, nk);
        int no = 2048 * 2048;
        split_kernel<<<no / 1024, 256>>>(o_w, (__nv_bfloat16*)p_woh, (__nv_bfloat16*)p_wol, no);
    }

    // 1. LoRA down-projection
    lora_t_kernel<<<MM, 192>>>(x, q_A, k_A, v_A);

    // 2. QKV GEMM (HMMA) -> g_qkv
    mma_gemm_kernel<<<dim3(NQKV / 128, MM / 128), 256, GEMM_SMEM>>>(
        (const __nv_bfloat16*)p_xh, (const __nv_bfloat16*)p_xl,
        (const __nv_bfloat16*)p_wqh, (const __nv_bfloat16*)p_wql,
        (float*)p_qkv, HHDIM, NQKV);

    // 3. bias + LoRA-up + RoPE + scatter (emits bf16 hi/lo q/k/v)
    rope_scatter_kernel<<<(MM * NQKV) / 256, 256>>>(
        cosb, sinb, q_b, k_b, v_b, q_Bm, k_Bm, v_Bm);

    // 4. HMMA causal flash attention -> g_ctx hi/lo
    flash_hmma_kernel<<<dim3(SS / 128, NHEADS, BB), 256, FA_SMEM>>>();

    // 5. output projection (HMMA) -> d_out
    mma_gemm_kernel<<<dim3(HHDIM / 128, MM / 128), 256, GEMM_SMEM>>>(
        (const __nv_bfloat16*)p_ch, (const __nv_bfloat16*)p_cl,
        (const __nv_bfloat16*)p_woh, (const __nv_bfloat16*)p_wol,
        out, HHDIM, HHDIM);
}

// round 5
// speedup vs baseline: 2.8209x; 1.0146x over previous
#include <cuda_runtime.h>
#include <cuda_bf16.h>
#include <cstdint>
#include <math.h>

// Problem constants
#define BB 2
#define SS 2048
#define HHDIM 2048
#define NHEADS 16
#define KVHEADS 4
#define HDIM 128
#define MM (BB*SS)              // 4096 rows
#define NQKV 3072
#define LORA_SCALE 2.0f
#define ATTN_SCALE 0.08838834764831845f

// ---------------------------------------------------------------------------
// Scratch (device globals)
// ---------------------------------------------------------------------------
__device__ __align__(16) float g_t[MM*48];
__device__ __align__(16) float g_qkv[(size_t)MM*NQKV];
__device__ __align__(16) __nv_bfloat16 g_qh[(size_t)BB*NHEADS*SS*HDIM];
__device__ __align__(16) __nv_bfloat16 g_ql[(size_t)BB*NHEADS*SS*HDIM];
__device__ __align__(16) __nv_bfloat16 g_kh[(size_t)BB*KVHEADS*SS*HDIM];
__device__ __align__(16) __nv_bfloat16 g_kl[(size_t)BB*KVHEADS*SS*HDIM];
__device__ __align__(16) __nv_bfloat16 g_vh[(size_t)BB*KVHEADS*SS*HDIM];
__device__ __align__(16) __nv_bfloat16 g_vl[(size_t)BB*KVHEADS*SS*HDIM];
__device__ __align__(16) __nv_bfloat16 g_xh[(size_t)MM*HHDIM];
__device__ __align__(16) __nv_bfloat16 g_xl[(size_t)MM*HHDIM];
__device__ __align__(16) __nv_bfloat16 g_wqkv_h[(size_t)NQKV*HHDIM];
__device__ __align__(16) __nv_bfloat16 g_wqkv_l[(size_t)NQKV*HHDIM];
__device__ __align__(16) __nv_bfloat16 g_wo_h[(size_t)HHDIM*HHDIM];
__device__ __align__(16) __nv_bfloat16 g_wo_l[(size_t)HHDIM*HHDIM];
__device__ __align__(16) __nv_bfloat16 g_ctx_h[(size_t)MM*HHDIM];
__device__ __align__(16) __nv_bfloat16 g_ctx_l[(size_t)MM*HHDIM];

// ---------------------------------------------------------------------------
// PTX helpers (baseline PTX only)
// ---------------------------------------------------------------------------
__device__ __forceinline__ uint32_t smem_to_u32(const void* p) {
    uint32_t a;
    asm("{ .reg .u64 t; cvta.to.shared.u64 t, %1; cvt.u32.u64 %0, t; }"
        : "=r"(a) : "l"(p));
    return a;
}
__device__ __forceinline__ void cp_async16(uint32_t sa, const void* gp) {
    asm volatile("cp.async.cg.shared.global [%0], [%1], 16;"
                 :: "r"(sa), "l"(gp) : "memory");
}
__device__ __forceinline__ void cp_commit() {
    asm volatile("cp.async.commit_group;" ::: "memory");
}
template <int N>
__device__ __forceinline__ void cp_wait() {
    asm volatile("cp.async.wait_group %0;" :: "n"(N) : "memory");
}
__device__ __forceinline__ void ldm_x4(uint32_t* r, uint32_t addr) {
    asm volatile("ldmatrix.sync.aligned.m8n8.x4.shared.b16 {%0,%1,%2,%3}, [%4];"
                 : "=r"(r[0]), "=r"(r[1]), "=r"(r[2]), "=r"(r[3]) : "r"(addr));
}
__device__ __forceinline__ void ldm_x4_t(uint32_t* r, uint32_t addr) {
    asm volatile("ldmatrix.sync.aligned.m8n8.x4.trans.shared.b16 {%0,%1,%2,%3}, [%4];"
                 : "=r"(r[0]), "=r"(r[1]), "=r"(r[2]), "=r"(r[3]) : "r"(addr));
}
__device__ __forceinline__ void mma_bf16(float* d, const uint32_t* a,
                                         uint32_t b0, uint32_t b1) {
    asm volatile(
        "mma.sync.aligned.m16n8k16.row.col.f32.bf16.bf16.f32 "
        "{%0,%1,%2,%3}, {%4,%5,%6,%7}, {%8,%9}, {%0,%1,%2,%3};"
        : "+f"(d[0]), "+f"(d[1]), "+f"(d[2]), "+f"(d[3])
        : "r"(a[0]), "r"(a[1]), "r"(a[2]), "r"(a[3]), "r"(b0), "r"(b1));
}
__device__ __forceinline__ void split2(float x, float y, uint32_t& h, uint32_t& l) {
    __nv_bfloat16 hx = __float2bfloat16_rn(x), hy = __float2bfloat16_rn(y);
    h = ((uint32_t)__bfloat16_as_ushort(hy) << 16) | __bfloat16_as_ushort(hx);
    __nv_bfloat16 lx = __float2bfloat16_rn(x - __bfloat162float(hx));
    __nv_bfloat16 ly = __float2bfloat16_rn(y - __bfloat162float(hy));
    l = ((uint32_t)__bfloat16_as_ushort(ly) << 16) | __bfloat16_as_ushort(lx);
}

// ---------------------------------------------------------------------------
// split fp32 -> bf16 hi + lo
// ---------------------------------------------------------------------------
__global__ __launch_bounds__(256) void split_kernel(
    const float* __restrict__ src,
    __nv_bfloat16* __restrict__ h,
    __nv_bfloat16* __restrict__ l, int n)
{
    int i = (blockIdx.x * 256 + threadIdx.x) * 4;
    if (i >= n) return;
    float4 v = *(const float4*)(src + i);
    float a[4] = {v.x, v.y, v.z, v.w};
    uint32_t hp[2], lp[2];
    split2(a[0], a[1], hp[0], lp[0]);
    split2(a[2], a[3], hp[1], lp[1]);
    *(uint2*)(h + i) = make_uint2(hp[0], hp[1]);
    *(uint2*)(l + i) = make_uint2(lp[0], lp[1]);
}

// ---------------------------------------------------------------------------
// HMMA GEMM: C[M,N] = A[M,K] @ B[N,K]^T via split-bf16 3-pass.
// Pass-major MMA ordering (reuse distance 4) to break RAW chains.
// ---------------------------------------------------------------------------
#define GSTRIDE 40
#define GTILE_B (128*GSTRIDE*2)
#define GSTAGE_B (4*GTILE_B)
#define GEMM_SMEM (2*GSTAGE_B)

__global__ __launch_bounds__(256)
void mma_gemm_kernel(const __nv_bfloat16* __restrict__ Ah,
                     const __nv_bfloat16* __restrict__ Al,
                     const __nv_bfloat16* __restrict__ Bh,
                     const __nv_bfloat16* __restrict__ Bl,
                     float* __restrict__ C, int Ksz, int Nsz)
{
    extern __shared__ char smem[];
    uint32_t sbase = smem_to_u32(smem);
    int tid = threadIdx.x;
    int wid = tid >> 5, lane = tid & 31;
    int bm = blockIdx.y * 128, bn = blockIdx.x * 128;
    int wm = wid >> 2, wn = wid & 3;

    const __nv_bfloat16* gsrc[4] = {
        Ah + (size_t)bm * Ksz, Al + (size_t)bm * Ksz,
        Bh + (size_t)bn * Ksz, Bl + (size_t)bn * Ksz };

    int r0c = tid >> 2;
    int c0c = tid & 3;
    auto issue_stage = [&](int s, int k0) {
        #pragma unroll
        for (int t = 0; t < 4; t++) {
            uint32_t tb = sbase + (uint32_t)s * GSTAGE_B + (uint32_t)t * GTILE_B;
            const __nv_bfloat16* g = gsrc[t] + k0;
            cp_async16(tb + (uint32_t)(r0c * 80 + c0c * 16),
                       g + (size_t)r0c * Ksz + c0c * 8);
            cp_async16(tb + (uint32_t)((r0c + 64) * 80 + c0c * 16),
                       g + (size_t)(r0c + 64) * Ksz + c0c * 8);
        }
        cp_commit();
    };

    float acc[4][4][4];
    #pragma unroll
    for (int i = 0; i < 4; i++)
        #pragma unroll
        for (int j = 0; j < 4; j++)
            #pragma unroll
            for (int r = 0; r < 4; r++) acc[i][j][r] = 0.f;

    int nIter = Ksz / 32;
    issue_stage(0, 0);

    for (int it = 0; it < nIter; it++) {
        int cur = it & 1;
        if (it + 1 < nIter) { issue_stage(cur ^ 1, (it + 1) * 32); cp_wait<1>(); }
        else cp_wait<0>();
        __syncthreads();

        uint32_t ahB = sbase + (uint32_t)cur * GSTAGE_B;
        uint32_t alB = ahB + GTILE_B;
        uint32_t bhB = ahB + 2 * GTILE_B;
        uint32_t blB = ahB + 3 * GTILE_B;

        #pragma unroll
        for (int ks = 0; ks < 2; ks++) {
            int k0 = ks * 16;
            uint32_t bh[8], bl[8];
            #pragma unroll
            for (int p = 0; p < 2; p++) {
                int brow = wn * 32 + p * 16 + ((lane >> 4) << 3) + (lane & 7);
                int bcol = k0 + ((lane >> 3) & 1) * 8;
                uint32_t off = (uint32_t)(brow * 80 + bcol * 2);
                ldm_x4(bh + p*4, bhB + off);
                ldm_x4(bl + p*4, blB + off);
            }
            #pragma unroll
            for (int mt = 0; mt < 4; mt++) {
                int arow = wm * 64 + mt * 16 + (lane & 15);
                int acol = k0 + ((lane >> 4) & 1) * 8;
                uint32_t off = (uint32_t)(arow * 80 + acol * 2);
                uint32_t a_h[4], a_l[4];
                ldm_x4(a_h, ahB + off);
                ldm_x4(a_l, alB + off);
                // pass-major: 4 independent accumulators per pass
                #pragma unroll
                for (int nt = 0; nt < 4; nt++)
                    mma_bf16(acc[mt][nt], a_h, bh[nt*2], bh[nt*2+1]);
                #pragma unroll
                for (int nt = 0; nt < 4; nt++)
                    mma_bf16(acc[mt][nt], a_h, bl[nt*2], bl[nt*2+1]);
                #pragma unroll
                for (int nt = 0; nt < 4; nt++)
                    mma_bf16(acc[mt][nt], a_l, bh[nt*2], bh[nt*2+1]);
            }
        }
        __syncthreads();
    }

    #pragma unroll
    for (int mt = 0; mt < 4; mt++) {
        int r0 = bm + wm * 64 + mt * 16 + (lane >> 2);
        #pragma unroll
        for (int nt = 0; nt < 4; nt++) {
            int c = bn + wn * 32 + nt * 8 + (lane & 3) * 2;
            *(float2*)&C[(size_t)r0 * Nsz + c]       = make_float2(acc[mt][nt][0], acc[mt][nt][1]);
            *(float2*)&C[(size_t)(r0 + 8) * Nsz + c] = make_float2(acc[mt][nt][2], acc[mt][nt][3]);
        }
    }
}

// ---------------------------------------------------------------------------
// t[row, 0..47] = x[row,:] @ [qA | kA | vA]
// ---------------------------------------------------------------------------
__global__ __launch_bounds__(192) void lora_t_kernel(
    const float* __restrict__ x,
    const float* __restrict__ qA,
    const float* __restrict__ kA,
    const float* __restrict__ vA)
{
    __shared__ float xs[HHDIM];
    __shared__ float part[48][4];
    int row = blockIdx.x;
    const float* xr = x + (size_t)row * HHDIM;
    for (int i = threadIdx.x; i < HHDIM; i += 192) xs[i] = xr[i];
    __syncthreads();

    int j   = threadIdx.x >> 2;
    int qtr = threadIdx.x & 3;
    const float* Acol; int jj;
    if (j < 16)       { Acol = qA; jj = j; }
    else if (j < 32)  { Acol = kA; jj = j - 16; }
    else              { Acol = vA; jj = j - 32; }

    float acc = 0.f;
    int h0 = qtr * 512;
    #pragma unroll 4
    for (int hh = h0; hh < h0 + 512; hh++)
        acc += xs[hh] * Acol[hh * 16 + jj];
    part[j][qtr] = acc;
    __syncthreads();

    if (threadIdx.x < 48) {
        int jo = threadIdx.x;
        g_t[(size_t)row * 48 + jo] = part[jo][0] + part[jo][1] + part[jo][2] + part[jo][3];
    }
}

// ---------------------------------------------------------------------------
// bias + LoRA + RoPE + scatter -> bf16 hi/lo q/k/v
// ---------------------------------------------------------------------------
__global__ __launch_bounds__(256) void rope_scatter_kernel(
    const float* __restrict__ cosb,
    const float* __restrict__ sinb,
    const float* __restrict__ q_b,
    const float* __restrict__ k_b,
    const float* __restrict__ v_b,
    const float* __restrict__ q_B,
    const float* __restrict__ k_B,
    const float* __restrict__ v_B)
{
    int idx = blockIdx.x * blockDim.x + threadIdx.x;
    int row = idx / NQKV;
    int c   = idx - row * NQKV;
    if (row >= MM) return;
    int b = row >> 11;
    int s = row & 2047;
    const float* trow = &g_t[(size_t)row * 48];
    const float* qkvrow = &g_qkv[(size_t)row * NQKV];

    if (c < 2048) {                       // Q
        int h = c >> 7, d = c & 127;
        if (d >= 64) return;
        float v1 = qkvrow[c]      + q_b[c];
        float v2 = qkvrow[c + 64] + q_b[c + 64];
        float a1 = 0.f, a2 = 0.f;
        #pragma unroll
        for (int j = 0; j < 16; j++) {
            float tj = trow[j];
            a1 += tj * q_B[j * 2048 + c];
            a2 += tj * q_B[j * 2048 + c + 64];
        }
        v1 += LORA_SCALE * a1; v2 += LORA_SCALE * a2;
        float cd  = cosb[row * HDIM + d],      sd  = sinb[row * HDIM + d];
        float cd2 = cosb[row * HDIM + d + 64], sd2 = sinb[row * HDIM + d + 64];
        float o1 = (v1 * cd  - v2 * sd)  * ATTN_SCALE;
        float o2 = (v2 * cd2 + v1 * sd2) * ATTN_SCALE;
        size_t base = (((size_t)b * NHEADS + h) * SS + s) * HDIM;
        __nv_bfloat16 h1 = __float2bfloat16_rn(o1);
        __nv_bfloat16 h2 = __float2bfloat16_rn(o2);
        g_qh[base + d]      = h1;
        g_qh[base + d + 64] = h2;
        g_ql[base + d]      = __float2bfloat16_rn(o1 - __bfloat162float(h1));
        g_ql[base + d + 64] = __float2bfloat16_rn(o2 - __bfloat162float(h2));
    } else if (c < 2560) {                // K
        int cc = c - 2048;
        int h = cc >> 7, d = cc & 127;
        if (d >= 64) return;
        float v1 = qkvrow[c]      + k_b[cc];
        float v2 = qkvrow[c + 64] + k_b[cc + 64];
        float a1 = 0.f, a2 = 0.f;
        #pragma unroll
        for (int j = 0; j < 16; j++) {
            float tj = trow[16 + j];
            a1 += tj * k_B[j * 512 + cc];
            a2 += tj * k_B[j * 512 + cc + 64];
        }
        v1 += LORA_SCALE * a1; v2 += LORA_SCALE * a2;
        float cd  = cosb[row * HDIM + d],      sd  = sinb[row * HDIM + d];
        float cd2 = cosb[row * HDIM + d + 64], sd2 = sinb[row * HDIM + d + 64];
        float o1 = v1 * cd  - v2 * sd;
        float o2 = v2 * cd2 + v1 * sd2;
        size_t base = (((size_t)b * KVHEADS + h) * SS + s) * HDIM;
        __nv_bfloat16 h1 = __float2bfloat16_rn(o1);
        __nv_bfloat16 h2 = __float2bfloat16_rn(o2);
        g_kh[base + d]      = h1;
        g_kh[base + d + 64] = h2;
        g_kl[base + d]      = __float2bfloat16_rn(o1 - __bfloat162float(h1));
        g_kl[base + d + 64] = __float2bfloat16_rn(o2 - __bfloat162float(h2));
    } else {                              // V
        int cc = c - 2560;
        int h = cc >> 7, d = cc & 127;
        float v = qkvrow[c] + v_b[cc];
        float a = 0.f;
        #pragma unroll
        for (int j = 0; j < 16; j++)
            a += trow[32 + j] * v_B[j * 512 + cc];
        v += LORA_SCALE * a;
        size_t base = (((size_t)b * KVHEADS + h) * SS + s) * HDIM;
        __nv_bfloat16 hv = __float2bfloat16_rn(v);
        g_vh[base + d] = hv;
        g_vl[base + d] = __float2bfloat16_rn(v - __bfloat162float(hv));
    }
}

// ---------------------------------------------------------------------------
// HMMA causal flash attention, pass-major MMA ordering.
// ---------------------------------------------------------------------------
#define FSTR 272
#define FQ_OFF 0
#define FQ_SZ  (128*FSTR)
#define FST_OFF (2*FQ_SZ)
#define FT_SZ  (64*FSTR)
#define FST_SZ (4*FT_SZ)
#define FA_SMEM (FST_OFF + 2*FST_SZ)

__global__ __launch_bounds__(256) void flash_hmma_kernel()
{
    extern __shared__ char smem[];
    uint32_t sb = smem_to_u32(smem);
    int qb = blockIdx.x, h = blockIdx.y, b = blockIdx.z;
    int kvh = h >> 2;
    int tid = threadIdx.x, wid = tid >> 5, lane = tid & 31;

    const __nv_bfloat16* Qh = g_qh + (((size_t)b * NHEADS + h) * SS + qb * 128) * HDIM;
    const __nv_bfloat16* Ql = g_ql + (((size_t)b * NHEADS + h) * SS + qb * 128) * HDIM;
    const __nv_bfloat16* kvsrc[4] = {
        g_kh + ((size_t)b * KVHEADS + kvh) * SS * HDIM,
        g_kl + ((size_t)b * KVHEADS + kvh) * SS * HDIM,
        g_vh + ((size_t)b * KVHEADS + kvh) * SS * HDIM,
        g_vl + ((size_t)b * KVHEADS + kvh) * SS * HDIM };

    #pragma unroll
    for (int t = 0; t < 16; t++) {
        int idx = t * 256 + tid;
        int arr = idx >> 11;
        int row = (idx >> 4) & 127;
        int ch  = idx & 15;
        const __nv_bfloat16* src = arr ? Ql : Qh;
        cp_async16(sb + (uint32_t)(arr * FQ_SZ + row * FSTR + ch * 16),
                   src + (size_t)row * 128 + ch * 8);
    }
    auto load_stage = [&](int s, int kv) {
        uint32_t base = sb + FST_OFF + (uint32_t)s * FST_SZ;
        #pragma unroll
        for (int t = 0; t < 16; t++) {
            int idx = t * 256 + tid;
            int arr = idx >> 10;
            int row = (idx >> 4) & 63;
            int ch  = idx & 15;
            cp_async16(base + (uint32_t)(arr * FT_SZ + row * FSTR + ch * 16),
                       kvsrc[arr] + (size_t)(kv * 64 + row) * 128 + ch * 8);
        }
        cp_commit();
    };
    load_stage(0, 0);

    float m[2] = {-1e30f, -1e30f}, lsum[2] = {0.f, 0.f};
    float oacc[16][4];
    #pragma unroll
    for (int g = 0; g < 16; g++)
        #pragma unroll
        for (int r = 0; r < 4; r++) oacc[g][r] = 0.f;

    int wrow0 = wid * 16;
    int rin = lane >> 2;
    int cpair = (lane & 3) * 2;
    int nkv = 2 * qb + 2;

    for (int kv = 0; kv < nkv; kv++) {
        int cur = kv & 1;
        if (kv + 1 < nkv) { load_stage(cur ^ 1, kv + 1); cp_wait<1>(); }
        else cp_wait<0>();
        __syncthreads();

        uint32_t stage = sb + FST_OFF + (uint32_t)cur * FST_SZ;
        uint32_t khB = stage, klB = stage + FT_SZ;
        uint32_t vhB = stage + 2 * FT_SZ, vlB = stage + 3 * FT_SZ;

        // ---- scores S = Q K^T, pass-major (8 indep accumulators) ----
        float sacc[8][4];
        #pragma unroll
        for (int nt = 0; nt < 8; nt++)
            #pragma unroll
            for (int r = 0; r < 4; r++) sacc[nt][r] = 0.f;

        #pragma unroll
        for (int ks = 0; ks < 8; ks++) {
            int k0 = ks * 16;
            uint32_t qoff = (uint32_t)((wrow0 + (lane & 15)) * FSTR
                                       + (k0 + ((lane >> 4) & 1) * 8) * 2);
            uint32_t qh4[4], ql4[4];
            ldm_x4(qh4, sb + FQ_OFF + qoff);
            ldm_x4(ql4, sb + FQ_SZ + qoff);
            uint32_t kh4[4][4], kl4[4][4];
            #pragma unroll
            for (int p = 0; p < 4; p++) {
                uint32_t koff = (uint32_t)((p * 16 + ((lane >> 4) << 3) + (lane & 7)) * FSTR
                                           + (k0 + ((lane >> 3) & 1) * 8) * 2);
                ldm_x4(kh4[p], khB + koff);
                ldm_x4(kl4[p], klB + koff);
            }
            #pragma unroll
            for (int p = 0; p < 4; p++) {
                mma_bf16(sacc[2*p],   qh4, kh4[p][0], kh4[p][1]);
                mma_bf16(sacc[2*p+1], qh4, kh4[p][2], kh4[p][3]);
            }
            #pragma unroll
            for (int p = 0; p < 4; p++) {
                mma_bf16(sacc[2*p],   qh4, kl4[p][0], kl4[p][1]);
                mma_bf16(sacc[2*p+1], qh4, kl4[p][2], kl4[p][3]);
            }
            #pragma unroll
            for (int p = 0; p < 4; p++) {
                mma_bf16(sacc[2*p],   ql4, kh4[p][0], kh4[p][1]);
                mma_bf16(sacc[2*p+1], ql4, kh4[p][2], kh4[p][3]);
            }
        }

        // ---- causal mask ----
        if (kv >= 2 * qb) {
            int row1 = qb * 128 + wrow0 + rin;
            #pragma unroll
            for (int nt = 0; nt < 8; nt++)
                #pragma unroll
                for (int r = 0; r < 4; r++) {
                    int key = kv * 64 + nt * 8 + cpair + (r & 1);
                    int row = (r < 2) ? row1 : row1 + 8;
                    if (key > row) sacc[nt][r] = -1e30f;
                }
        }

        // ---- online softmax ----
        #pragma unroll
        for (int rh = 0; rh < 2; rh++) {
            float rmax = -1e30f;
            #pragma unroll
            for (int nt = 0; nt < 8; nt++)
                rmax = fmaxf(rmax, fmaxf(sacc[nt][rh*2], sacc[nt][rh*2+1]));
            rmax = fmaxf(rmax, __shfl_xor_sync(0xffffffffu, rmax, 1));
            rmax = fmaxf(rmax, __shfl_xor_sync(0xffffffffu, rmax, 2));
            float mn = fmaxf(m[rh], rmax);
            float corr = __expf(m[rh] - mn);
            m[rh] = mn;
            float rs = 0.f;
            #pragma unroll
            for (int nt = 0; nt < 8; nt++) {
                float p0 = __expf(sacc[nt][rh*2]   - mn);
                float p1 = __expf(sacc[nt][rh*2+1] - mn);
                sacc[nt][rh*2] = p0; sacc[nt][rh*2+1] = p1;
                rs += p0 + p1;
            }
            rs += __shfl_xor_sync(0xffffffffu, rs, 1);
            rs += __shfl_xor_sync(0xffffffffu, rs, 2);
            lsum[rh] = lsum[rh] * corr + rs;
            #pragma unroll
            for (int g = 0; g < 16; g++) {
                oacc[g][rh*2]   *= corr;
                oacc[g][rh*2+1] *= corr;
            }
        }

        // ---- pack P ----
        uint32_t pfh[4][4], pfl[4][4];
        #pragma unroll
        for (int j = 0; j < 4; j++) {
            split2(sacc[2*j][0],   sacc[2*j][1],   pfh[j][0], pfl[j][0]);
            split2(sacc[2*j][2],   sacc[2*j][3],   pfh[j][1], pfl[j][1]);
            split2(sacc[2*j+1][0], sacc[2*j+1][1], pfh[j][2], pfl[j][2]);
            split2(sacc[2*j+1][2], sacc[2*j+1][3], pfh[j][3], pfl[j][3]);
        }

        // ---- O += P V, pass-major over halves of g ----
        #pragma unroll
        for (int j = 0; j < 4; j++) {
            int k0 = j * 16;
            #pragma unroll
            for (int gh = 0; gh < 2; gh++) {
                uint32_t vh4[4][4], vl4[4][4];
                #pragma unroll
                for (int p = 0; p < 4; p++) {
                    int g = gh * 4 + p;
                    uint32_t voff = (uint32_t)((k0 + ((lane >> 3) & 1) * 8 + (lane & 7)) * FSTR
                                               + (g * 16 + ((lane >> 4) & 1) * 8) * 2);
                    ldm_x4_t(vh4[p], vhB + voff);
                    ldm_x4_t(vl4[p], vlB + voff);
                }
                #pragma unroll
                for (int p = 0; p < 4; p++) {
                    int g = gh * 4 + p;
                    mma_bf16(oacc[2*g],   pfh[j], vh4[p][0], vh4[p][1]);
                    mma_bf16(oacc[2*g+1], pfh[j], vh4[p][2], vh4[p][3]);
                }
                #pragma unroll
                for (int p = 0; p < 4; p++) {
                    int g = gh * 4 + p;
                    mma_bf16(oacc[2*g],   pfh[j], vl4[p][0], vl4[p][1]);
                    mma_bf16(oacc[2*g+1], pfh[j], vl4[p][2], vl4[p][3]);
                }
                #pragma unroll
                for (int p = 0; p < 4; p++) {
                    int g = gh * 4 + p;
                    mma_bf16(oacc[2*g],   pfl[j], vh4[p][0], vh4[p][1]);
                    mma_bf16(oacc[2*g+1], pfl[j], vh4[p][2], vh4[p][3]);
                }
            }
        }
        __syncthreads();
    }

    // ---- epilogue ----
    float inv0 = 1.f / lsum[0], inv1 = 1.f / lsum[1];
    int row1 = qb * 128 + wrow0 + rin;
    #pragma unroll
    for (int g = 0; g < 16; g++) {
        uint32_t h2, l2;
        size_t off0 = ((size_t)b * SS + row1) * HHDIM + h * 128 + g * 8 + cpair;
        split2(oacc[g][0] * inv0, oacc[g][1] * inv0, h2, l2);
        *(uint32_t*)(g_ctx_h + off0) = h2;
        *(uint32_t*)(g_ctx_l + off0) = l2;
        size_t off1 = off0 + (size_t)8 * HHDIM;
        split2(oacc[g][2] * inv1, oacc[g][3] * inv1, h2, l2);
        *(uint32_t*)(g_ctx_h + off1) = h2;
        *(uint32_t*)(g_ctx_l + off1) = l2;
    }
}

// ---------------------------------------------------------------------------
// Launch
// ---------------------------------------------------------------------------
extern "C" void kernel_launch(void* const* d_in, const int* in_sizes, int n_in,
                              void* d_out, int out_size)
{
    const float* x    = (const float*)d_in[0];
    const float* cosb = (const float*)d_in[1];
    const float* sinb = (const float*)d_in[2];
    const float* q_w  = (const float*)d_in[4];
    const float* k_w  = (const float*)d_in[5];
    const float* v_w  = (const float*)d_in[6];
    const float* q_b  = (const float*)d_in[7];
    const float* k_b  = (const float*)d_in[8];
    const float* v_b  = (const float*)d_in[9];
    const float* q_A  = (const float*)d_in[10];
    const float* q_Bm = (const float*)d_in[11];
    const float* k_A  = (const float*)d_in[12];
    const float* k_Bm = (const float*)d_in[13];
    const float* v_A  = (const float*)d_in[14];
    const float* v_Bm = (const float*)d_in[15];
    const float* o_w  = (const float*)d_in[16];
    float* out = (float*)d_out;

    void *p_xh, *p_xl, *p_wqh, *p_wql, *p_woh, *p_wol, *p_qkv, *p_ch, *p_cl;
    cudaGetSymbolAddress(&p_xh,  g_xh);
    cudaGetSymbolAddress(&p_xl,  g_xl);
    cudaGetSymbolAddress(&p_wqh, g_wqkv_h);
    cudaGetSymbolAddress(&p_wql, g_wqkv_l);
    cudaGetSymbolAddress(&p_woh, g_wo_h);
    cudaGetSymbolAddress(&p_wol, g_wo_l);
    cudaGetSymbolAddress(&p_qkv, g_qkv);
    cudaGetSymbolAddress(&p_ch,  g_ctx_h);
    cudaGetSymbolAddress(&p_cl,  g_ctx_l);

    cudaFuncSetAttribute(mma_gemm_kernel,
                         cudaFuncAttributeMaxDynamicSharedMemorySize, GEMM_SMEM);
    cudaFuncSetAttribute(flash_hmma_kernel,
                         cudaFuncAttributeMaxDynamicSharedMemorySize, FA_SMEM);

    // 0. split fp32 -> bf16 hi/lo
    {
        int n = MM * HHDIM;
        split_kernel<<<n / 1024, 256>>>(x, (__nv_bfloat16*)p_xh, (__nv_bfloat16*)p_xl, n);
        int nq = 2048 * 2048;
        split_kernel<<<nq / 1024, 256>>>(q_w, (__nv_bfloat16*)p_wqh, (__nv_bfloat16*)p_wql, nq);
        int nk = 512 * 2048;
        split_kernel<<<nk / 1024, 256>>>(k_w, (__nv_bfloat16*)p_wqh + (size_t)2048*2048,
                                         (__nv_bfloat16*)p_wql + (size_t)2048*2048, nk);
        split_kernel<<<nk / 1024, 256>>>(v_w, (__nv_bfloat16*)p_wqh + (size_t)2560*2048,
                                         (__nv_bfloat16*)p_wql + (size_t)2560*2048, nk);
        int no = 2048 * 2048;
        split_kernel<<<no / 1024, 256>>>(o_w, (__nv_bfloat16*)p_woh, (__nv_bfloat16*)p_wol, no);
    }

    // 1. LoRA down-projection
    lora_t_kernel<<<MM, 192>>>(x, q_A, k_A, v_A);

    // 2. QKV GEMM -> g_qkv
    mma_gemm_kernel<<<dim3(NQKV / 128, MM / 128), 256, GEMM_SMEM>>>(
        (const __nv_bfloat16*)p_xh, (const __nv_bfloat16*)p_xl,
        (const __nv_bfloat16*)p_wqh, (const __nv_bfloat16*)p_wql,
        (float*)p_qkv, HHDIM, NQKV);

    // 3. bias + LoRA-up + RoPE + scatter
    rope_scatter_kernel<<<(MM * NQKV) / 256, 256>>>(
        cosb, sinb, q_b, k_b, v_b, q_Bm, k_Bm, v_Bm);

    // 4. HMMA causal flash attention
    flash_hmma_kernel<<<dim3(SS / 128, NHEADS, BB), 256, FA_SMEM>>>();

    // 5. output projection -> d_out
    mma_gemm_kernel<<<dim3(HHDIM / 128, MM / 128), 256, GEMM_SMEM>>>(
        (const __nv_bfloat16*)p_ch, (const __nv_bfloat16*)p_cl,
        (const __nv_bfloat16*)p_woh, (const __nv_bfloat16*)p_wol,
        out, HHDIM, HHDIM);
}